// round 13
// baseline (speedup 1.0000x reference)
#include <cuda_runtime.h>
#include <cuda_bf16.h>
#include <cuda_fp16.h>
#include <math.h>
#include <stdint.h>

// Problem constants
#define Bsz 4
#define Tsz 2048
#define Csz 1024
#define Hsz 16
#define Dsz 64
#define M1 (Bsz * Tsz)        // 8192
#define KD 1024               // real K for all GEMMs

// ---------------------------------------------------------------------------
// Device scratch (allocation-free)
// ---------------------------------------------------------------------------
__device__ __nv_bfloat16 g_qh[Bsz * Hsz * Tsz * Dsz];  // (B,H,T,D)  (scaled by log2e)
__device__ __nv_bfloat16 g_ql[Bsz * Hsz * Tsz * Dsz];
__device__ __nv_bfloat16 g_kh[Bsz * Hsz * Tsz * Dsz];
__device__ __nv_bfloat16 g_kl[Bsz * Hsz * Tsz * Dsz];
__device__ __half        g_vt[Bsz * Hsz * Dsz * Tsz];  // (B,H,D,T) fp16

__device__ __nv_bfloat16 g_xh[M1 * KD];      // x bf16 hi/lo (QK GEMM)
__device__ __nv_bfloat16 g_xl[M1 * KD];
__device__ __half        g_xhf[M1 * KD];     // x fp16 hi (V GEMM, single-term)
__device__ __half        g_yh[M1 * KD];      // attn out fp16 (single-term outproj)
__device__ __nv_bfloat16 g_wqkh[2 * Csz * KD]; // W_q|k^T bf16 hi/lo
__device__ __nv_bfloat16 g_wqkl[2 * Csz * KD];
__device__ __half        g_wvh[Csz * KD];      // W_v^T fp16
__device__ __half        g_woh[Csz * KD];      // W_out^T fp16

// ---------------------------------------------------------------------------
__device__ __forceinline__ uint32_t smem_u32(const void* p) {
    uint32_t a;
    asm("{ .reg .u64 t; cvta.to.shared.u64 t, %1; cvt.u32.u64 %0, t; }" : "=r"(a) : "l"(p));
    return a;
}
__device__ __forceinline__ float ex2f(float x) {
    float r; asm("ex2.approx.ftz.f32 %0, %1;" : "=f"(r) : "f"(x)); return r;
}
__device__ __forceinline__ void split2(float v, __nv_bfloat16& hi, __nv_bfloat16& lo) {
    hi = __float2bfloat16(v);
    lo = __float2bfloat16(v - __bfloat162float(hi));
}

struct RopeTab { float inv[32]; };
#define LOG2E 1.44269504088896f

// ---------------------------------------------------------------------------
// Merged conversion kernel (one launch)
// ---------------------------------------------------------------------------
#define NB_SPLITX 8192
#define NB_WQKV   3072   // 96 x 32
#define NB_WOUT   1024   // 32 x 32

__global__ __launch_bounds__(256)
void convert_kernel(const float* __restrict__ x, const float* __restrict__ Wqkv,
                    const float* __restrict__ Wout)
{
    int blk = blockIdx.x;
    if (blk < NB_SPLITX) {
        int i = (blk * 256 + threadIdx.x) * 4;
        float4 v = *(const float4*)&x[i];
        float vv[4] = { v.x, v.y, v.z, v.w };
        __nv_bfloat16 bh[4], bl[4];
        __half fh[4];
#pragma unroll
        for (int q = 0; q < 4; q++) {
            split2(vv[q], bh[q], bl[q]);
            fh[q] = __float2half(vv[q]);
        }
        *(__nv_bfloat162*)&g_xh[i]     = __nv_bfloat162(bh[0], bh[1]);
        *(__nv_bfloat162*)&g_xh[i + 2] = __nv_bfloat162(bh[2], bh[3]);
        *(__nv_bfloat162*)&g_xl[i]     = __nv_bfloat162(bl[0], bl[1]);
        *(__nv_bfloat162*)&g_xl[i + 2] = __nv_bfloat162(bl[2], bl[3]);
        *(__half2*)&g_xhf[i]     = __half2(fh[0], fh[1]);
        *(__half2*)&g_xhf[i + 2] = __half2(fh[2], fh[3]);
        return;
    }

    __shared__ float ts[32][33];
    int ty = threadIdx.x >> 5, tx = threadIdx.x & 31;

    if (blk < NB_SPLITX + NB_WQKV) {
        int b2 = blk - NB_SPLITX;
        int n0 = (b2 % 96) * 32, k0 = (b2 / 96) * 32;
#pragma unroll
        for (int r = 0; r < 4; r++) {
            int row = ty + r * 8;
            ts[row][tx] = Wqkv[(size_t)(k0 + row) * (3 * Csz) + n0 + tx];
        }
        __syncthreads();
#pragma unroll
        for (int r = 0; r < 4; r++) {
            int row = ty + r * 8;
            int n = n0 + row;
            float v = ts[tx][row];
            if (n < 2048) {
                __nv_bfloat16 h, l; split2(v, h, l);
                g_wqkh[(size_t)n * KD + k0 + tx] = h;
                g_wqkl[(size_t)n * KD + k0 + tx] = l;
            } else {
                g_wvh[(size_t)(n - 2048) * KD + k0 + tx] = __float2half(v);
            }
        }
    } else {
        int b2 = blk - NB_SPLITX - NB_WQKV;
        int n0 = (b2 % 32) * 32, k0 = (b2 / 32) * 32;
#pragma unroll
        for (int r = 0; r < 4; r++) {
            int row = ty + r * 8;
            ts[row][tx] = Wout[(size_t)(k0 + row) * Csz + n0 + tx];
        }
        __syncthreads();
#pragma unroll
        for (int r = 0; r < 4; r++) {
            int row = ty + r * 8;
            g_woh[(size_t)(n0 + row) * KD + k0 + tx] = __float2half(ts[tx][row]);
        }
    }
}

// ---------------------------------------------------------------------------
// HMMA / async macros
// ---------------------------------------------------------------------------
#define LDM_X4(r0, r1, r2, r3, addr) \
    asm volatile("ldmatrix.sync.aligned.m8n8.x4.shared.b16 {%0,%1,%2,%3}, [%4];" \
                 : "=r"(r0), "=r"(r1), "=r"(r2), "=r"(r3) : "r"(addr))

#define MMA_BF(c0, c1, c2, c3, a0, a1, a2, a3, b0, b1) \
    asm volatile("mma.sync.aligned.m16n8k16.row.col.f32.bf16.bf16.f32 " \
                 "{%0,%1,%2,%3}, {%4,%5,%6,%7}, {%8,%9}, {%0,%1,%2,%3};" \
                 : "+f"(c0), "+f"(c1), "+f"(c2), "+f"(c3) \
                 : "r"(a0), "r"(a1), "r"(a2), "r"(a3), "r"(b0), "r"(b1))

#define MMA_FP(c0, c1, c2, c3, a0, a1, a2, a3, b0, b1) \
    asm volatile("mma.sync.aligned.m16n8k16.row.col.f32.f16.f16.f32 " \
                 "{%0,%1,%2,%3}, {%4,%5,%6,%7}, {%8,%9}, {%0,%1,%2,%3};" \
                 : "+f"(c0), "+f"(c1), "+f"(c2), "+f"(c3) \
                 : "r"(a0), "r"(a1), "r"(a2), "r"(a3), "r"(b0), "r"(b1))

#define CP16(sa, gp) \
    asm volatile("cp.async.cg.shared.global [%0], [%1], 16;" :: "r"(sa), "l"(gp))
#define CP_COMMIT() asm volatile("cp.async.commit_group;" ::: "memory")
#define CP_WAITG(n) asm volatile("cp.async.wait_group %0;" :: "n"(n) : "memory")

#define SWOFF(row, c) ((row) * 128 + (((c) ^ ((row) & 7)) * 16))
#define SWOFF32(row, c) ((row) * 64 + ((((c) ^ ((row) & 3)) ^ (((row) >> 2) & 1)) * 16))

#define TILE32 8192
#define TRS 272
#define QKV_SMEM (3 * 4 * TILE32)   // 98304

// ---------------------------------------------------------------------------
// Merged QKV GEMM. grid (24, 64).
// ---------------------------------------------------------------------------
__global__ __launch_bounds__(256, 2)
void qkv_gemm_kernel(const float* __restrict__ bqkv, RopeTab tab)
{
    extern __shared__ char smem_all[];

    const int tid = threadIdx.x;
    const int lane = tid & 31;
    const int wid = tid >> 5;
    const int wm = wid >> 1;
    const int wn = wid & 1;
    const int m0 = blockIdx.y * 128;
    const uint32_t sbase = smem_u32(smem_all);
    const uint32_t lrow = lane & 15;
    const int nk = KD / 32;             // 32

    float acc[2][8][4];
#pragma unroll
    for (int i = 0; i < 2; i++)
#pragma unroll
        for (int j = 0; j < 8; j++)
#pragma unroll
            for (int q = 0; q < 4; q++) acc[i][j][q] = 0.f;

    if (blockIdx.x < 16) {
        // ================= QK path: bf16 3-term =================
        const int n0 = blockIdx.x * 128;
        constexpr int STAGE = 4 * TILE32;

        auto issue_stage = [&](int kt) {
            if (kt < nk) {
                const uint32_t base = sbase + (kt % 3) * STAGE;
                const __nv_bfloat16* pAh = g_xh + (size_t)m0 * KD + kt * 32;
                const __nv_bfloat16* pAl = g_xl + (size_t)m0 * KD + kt * 32;
                const __nv_bfloat16* pBh = g_wqkh + (size_t)n0 * KD + kt * 32;
                const __nv_bfloat16* pBl = g_wqkl + (size_t)n0 * KD + kt * 32;
#pragma unroll
                for (int i = 0; i < 2; i++) {
                    int chunk = tid + i * 256;
                    int row = chunk >> 2, c = chunk & 3;
                    uint32_t off = SWOFF32(row, c);
                    const size_t g = (size_t)row * KD + c * 8;
                    CP16(base + off,              pAh + g);
                    CP16(base + TILE32 + off,     pAl + g);
                    CP16(base + 2 * TILE32 + off, pBh + g);
                    CP16(base + 3 * TILE32 + off, pBl + g);
                }
            }
            CP_COMMIT();
        };

        issue_stage(0);
        issue_stage(1);

        for (int kt = 0; kt < nk; kt++) {
            CP_WAITG(1);
            __syncthreads();
            const uint32_t aBase  = sbase + (kt % 3) * STAGE;
            const uint32_t alBase = aBase + TILE32;
            const uint32_t bBase  = aBase + 2 * TILE32;
            const uint32_t blBase = aBase + 3 * TILE32;
#pragma unroll
            for (int ks = 0; ks < 2; ks++) {
                const uint32_t cc = ks * 2 + (lane >> 4);
                uint32_t ahf[2][4], alf[2][4];
#pragma unroll
                for (int i = 0; i < 2; i++) {
                    int row = wm * 32 + i * 16 + lrow;
                    LDM_X4(ahf[i][0], ahf[i][1], ahf[i][2], ahf[i][3], aBase  + SWOFF32(row, cc));
                    LDM_X4(alf[i][0], alf[i][1], alf[i][2], alf[i][3], alBase + SWOFF32(row, cc));
                }
                if (ks == 0) issue_stage(kt + 2);
#pragma unroll
                for (int j2 = 0; j2 < 4; j2++) {
                    int row = wn * 64 + j2 * 16 + lrow;
                    uint32_t bh4[4], bl4[4];
                    LDM_X4(bh4[0], bh4[1], bh4[2], bh4[3], bBase  + SWOFF32(row, cc));
                    LDM_X4(bl4[0], bl4[1], bl4[2], bl4[3], blBase + SWOFF32(row, cc));
#pragma unroll
                    for (int o = 0; o < 2; o++)
#pragma unroll
                        for (int i = 0; i < 2; i++) {
                            int j = 2 * j2 + o;
                            MMA_BF(acc[i][j][0], acc[i][j][1], acc[i][j][2], acc[i][j][3],
                                   ahf[i][0], ahf[i][1], ahf[i][2], ahf[i][3], bh4[o], bh4[o + 2]);
                        }
#pragma unroll
                    for (int o = 0; o < 2; o++)
#pragma unroll
                        for (int i = 0; i < 2; i++) {
                            int j = 2 * j2 + o;
                            MMA_BF(acc[i][j][0], acc[i][j][1], acc[i][j][2], acc[i][j][3],
                                   alf[i][0], alf[i][1], alf[i][2], alf[i][3], bh4[o], bh4[o + 2]);
                        }
#pragma unroll
                    for (int o = 0; o < 2; o++)
#pragma unroll
                        for (int i = 0; i < 2; i++) {
                            int j = 2 * j2 + o;
                            MMA_BF(acc[i][j][0], acc[i][j][1], acc[i][j][2], acc[i][j][3],
                                   ahf[i][0], ahf[i][1], ahf[i][2], ahf[i][3], bl4[o], bl4[o + 2]);
                        }
                }
            }
        }

        // Epilogue: RoPE + split; q additionally scaled by log2e
        const int which = n0 >> 10;          // 0=q, 1=k
        const float l2e = (which == 0) ? LOG2E : 1.f;
        __nv_bfloat16* GH = (which == 0) ? g_qh : g_kh;
        __nv_bfloat16* GL = (which == 0) ? g_ql : g_kl;
        const int b = m0 >> 11;
        const int hh = ((n0 + wn * 64) & 1023) >> 6;
        const int bh = b * Hsz + hh;
        const int dbase = 2 * (lane & 3);
#pragma unroll
        for (int i = 0; i < 2; i++) {
#pragma unroll
            for (int hf = 0; hf < 2; hf++) {
                int m = m0 + wm * 32 + (lane >> 2) + i * 16 + hf * 8;
                int t = m & (Tsz - 1);
                size_t baseo = ((size_t)bh * Tsz + t) * Dsz;
#pragma unroll
                for (int j = 0; j < 4; j++) {
                    int n = n0 + wn * 64 + dbase + j * 8;
                    int d = n & 63;
                    float lowx  = acc[i][j][hf * 2]     + bqkv[n];
                    float lowy  = acc[i][j][hf * 2 + 1] + bqkv[n + 1];
                    float highx = acc[i][j + 4][hf * 2]     + bqkv[n + 32];
                    float highy = acc[i][j + 4][hf * 2 + 1] + bqkv[n + 33];
                    float c0f, s0f, c1f, s1f;
                    sincosf((float)t * tab.inv[d],     &s0f, &c0f);
                    sincosf((float)t * tab.inv[d + 1], &s1f, &c1f);
                    float nlx = (lowx * c0f - highx * s0f) * l2e;
                    float nhx = (highx * c0f + lowx * s0f) * l2e;
                    float nly = (lowy * c1f - highy * s1f) * l2e;
                    float nhy = (highy * c1f + lowy * s1f) * l2e;
                    __nv_bfloat16 hlx, llx, hly, lly, hhx, lhx, hhy, lhy;
                    split2(nlx, hlx, llx); split2(nly, hly, lly);
                    split2(nhx, hhx, lhx); split2(nhy, hhy, lhy);
                    *(__nv_bfloat162*)&GH[baseo + d]      = __nv_bfloat162(hlx, hly);
                    *(__nv_bfloat162*)&GL[baseo + d]      = __nv_bfloat162(llx, lly);
                    *(__nv_bfloat162*)&GH[baseo + d + 32] = __nv_bfloat162(hhx, hhy);
                    *(__nv_bfloat162*)&GL[baseo + d + 32] = __nv_bfloat162(lhx, lhy);
                }
            }
        }
    } else {
        // ================= V path: fp16 single-term =================
        const int n0 = (blockIdx.x - 16) * 128;
        constexpr int STAGE = 2 * TILE32;

        auto issue_stage = [&](int kt) {
            if (kt < nk) {
                const uint32_t base = sbase + (kt % 3) * STAGE;
                const __half* pAh = g_xhf + (size_t)m0 * KD + kt * 32;
                const __half* pBh = g_wvh + (size_t)n0 * KD + kt * 32;
#pragma unroll
                for (int i = 0; i < 2; i++) {
                    int chunk = tid + i * 256;
                    int row = chunk >> 2, c = chunk & 3;
                    uint32_t off = SWOFF32(row, c);
                    const size_t g = (size_t)row * KD + c * 8;
                    CP16(base + off,          pAh + g);
                    CP16(base + TILE32 + off, pBh + g);
                }
            }
            CP_COMMIT();
        };

        issue_stage(0);
        issue_stage(1);

        for (int kt = 0; kt < nk; kt++) {
            CP_WAITG(1);
            __syncthreads();
            const uint32_t aBase = sbase + (kt % 3) * STAGE;
            const uint32_t bBase = aBase + TILE32;
#pragma unroll
            for (int ks = 0; ks < 2; ks++) {
                const uint32_t cc = ks * 2 + (lane >> 4);
                uint32_t ahf[2][4];
#pragma unroll
                for (int i = 0; i < 2; i++) {
                    int row = wm * 32 + i * 16 + lrow;
                    LDM_X4(ahf[i][0], ahf[i][1], ahf[i][2], ahf[i][3], aBase + SWOFF32(row, cc));
                }
                if (ks == 0) issue_stage(kt + 2);
#pragma unroll
                for (int j2 = 0; j2 < 4; j2++) {
                    int row = wn * 64 + j2 * 16 + lrow;
                    uint32_t bh4[4];
                    LDM_X4(bh4[0], bh4[1], bh4[2], bh4[3], bBase + SWOFF32(row, cc));
#pragma unroll
                    for (int o = 0; o < 2; o++)
#pragma unroll
                        for (int i = 0; i < 2; i++) {
                            int j = 2 * j2 + o;
                            MMA_FP(acc[i][j][0], acc[i][j][1], acc[i][j][2], acc[i][j][3],
                                   ahf[i][0], ahf[i][1], ahf[i][2], ahf[i][3], bh4[o], bh4[o + 2]);
                        }
                }
            }
        }

        // V epilogue: smem transpose -> g_vt (B,H,D,T) fp16
        const int b = m0 >> 11;
        const int t0 = m0 & (Tsz - 1);
        __half* trs = (__half*)smem_all;
        __syncthreads();
#pragma unroll
        for (int i = 0; i < 2; i++)
#pragma unroll
            for (int hf = 0; hf < 2; hf++) {
                int ml = wm * 32 + (lane >> 2) + i * 16 + hf * 8;
#pragma unroll
                for (int j = 0; j < 8; j++) {
                    int nl = wn * 64 + 2 * (lane & 3) + j * 8;
                    float vx = acc[i][j][hf * 2]     + bqkv[2048 + n0 + nl];
                    float vy = acc[i][j][hf * 2 + 1] + bqkv[2048 + n0 + nl + 1];
                    trs[nl * 136 + ml]       = __float2half(vx);
                    trs[(nl + 1) * 136 + ml] = __float2half(vy);
                }
            }
        __syncthreads();
#pragma unroll
        for (int rr = 0; rr < 8; rr++) {
            int row = (tid >> 4) + rr * 16;
            int chunk = tid & 15;
            int n = n0 + row;
            int hh = n >> 6;
            int d = n & 63;
            float4 v = *(float4*)((char*)trs + row * TRS + chunk * 16);
            *(float4*)&g_vt[((size_t)(b * Hsz + hh) * Dsz + d) * Tsz + t0 + chunk * 8] = v;
        }
    }
}

// ---------------------------------------------------------------------------
// Output projection: fp16 single-term (yh @ Woh). occ-3 for latency hiding.
// ---------------------------------------------------------------------------
#define OUTP_SMEM (3 * 2 * TILE32)

__global__ __launch_bounds__(256, 3)
void outproj_kernel(const float* __restrict__ bias, float* __restrict__ Cout)
{
    extern __shared__ char smem_all[];
    const int tid = threadIdx.x;
    const int lane = tid & 31;
    const int wid = tid >> 5;
    const int wm = wid >> 1;
    const int wn = wid & 1;
    const int m0 = blockIdx.y * 128;
    const int n0 = blockIdx.x * 128;
    const uint32_t sbase = smem_u32(smem_all);
    const uint32_t lrow = lane & 15;
    const int nk = KD / 32;
    constexpr int STAGE = 2 * TILE32;

    auto issue_stage = [&](int kt) {
        if (kt < nk) {
            const uint32_t base = sbase + (kt % 3) * STAGE;
            const __half* pAh = g_yh + (size_t)m0 * KD + kt * 32;
            const __half* pBh = g_woh + (size_t)n0 * KD + kt * 32;
#pragma unroll
            for (int i = 0; i < 2; i++) {
                int chunk = tid + i * 256;
                int row = chunk >> 2, c = chunk & 3;
                uint32_t off = SWOFF32(row, c);
                const size_t g = (size_t)row * KD + c * 8;
                CP16(base + off,          pAh + g);
                CP16(base + TILE32 + off, pBh + g);
            }
        }
        CP_COMMIT();
    };

    issue_stage(0);
    issue_stage(1);

    float acc[2][8][4];
#pragma unroll
    for (int i = 0; i < 2; i++)
#pragma unroll
        for (int j = 0; j < 8; j++)
#pragma unroll
            for (int q = 0; q < 4; q++) acc[i][j][q] = 0.f;

    for (int kt = 0; kt < nk; kt++) {
        CP_WAITG(1);
        __syncthreads();
        const uint32_t aBase = sbase + (kt % 3) * STAGE;
        const uint32_t bBase = aBase + TILE32;
#pragma unroll
        for (int ks = 0; ks < 2; ks++) {
            const uint32_t cc = ks * 2 + (lane >> 4);
            uint32_t ahf[2][4];
#pragma unroll
            for (int i = 0; i < 2; i++) {
                int row = wm * 32 + i * 16 + lrow;
                LDM_X4(ahf[i][0], ahf[i][1], ahf[i][2], ahf[i][3], aBase + SWOFF32(row, cc));
            }
            if (ks == 0) issue_stage(kt + 2);
#pragma unroll
            for (int j2 = 0; j2 < 4; j2++) {
                int row = wn * 64 + j2 * 16 + lrow;
                uint32_t bh4[4];
                LDM_X4(bh4[0], bh4[1], bh4[2], bh4[3], bBase + SWOFF32(row, cc));
#pragma unroll
                for (int o = 0; o < 2; o++)
#pragma unroll
                    for (int i = 0; i < 2; i++) {
                        int j = 2 * j2 + o;
                        MMA_FP(acc[i][j][0], acc[i][j][1], acc[i][j][2], acc[i][j][3],
                               ahf[i][0], ahf[i][1], ahf[i][2], ahf[i][3], bh4[o], bh4[o + 2]);
                    }
            }
        }
    }

    const int mwb = m0 + wm * 32 + (lane >> 2);
    const int nwb = n0 + wn * 64 + 2 * (lane & 3);
#pragma unroll
    for (int i = 0; i < 2; i++)
#pragma unroll
        for (int j = 0; j < 8; j++) {
            int n = nwb + j * 8;
            float bx = bias[n], by = bias[n + 1];
#pragma unroll
            for (int hf = 0; hf < 2; hf++) {
                int m = mwb + i * 16 + hf * 8;
                *(float2*)&Cout[(size_t)m * Csz + n] =
                    make_float2(acc[i][j][hf * 2] + bx, acc[i][j][hf * 2 + 1] + by);
            }
        }
}

// ---------------------------------------------------------------------------
// HMMA flash attention, causal. BM=128 (8 warps x 16 rows), BN=64, D=64.
// S: bf16x3 (ex2 softmax). PV: fp16 single-term. 3-stage KV; per-warp skip.
// ---------------------------------------------------------------------------
#define KVSTAGE 24576
#define ATT_SMEM (32768 + 3 * KVSTAGE)      // 106496

__global__ __launch_bounds__(256, 2)
void attn_hmma_kernel()
{
    extern __shared__ char asmem[];

    const int tid = threadIdx.x;
    const int lane = tid & 31;
    const int wid = tid >> 5;              // 0..7
    const int q0 = (int)(gridDim.x - 1 - blockIdx.x) * 128;
    const int bh = blockIdx.y;
    const uint32_t sb = smem_u32(asmem);
    const uint32_t qhB = sb, qlB = sb + 16384;
    const uint32_t lrow = lane & 15;
    const int nt = q0 / 64 + 2;
    const int wrow_max = q0 + wid * 16 + 15;

    {
        const size_t qg = ((size_t)bh * Tsz + q0) * Dsz;
#pragma unroll
        for (int i = 0; i < 4; i++) {
            int chunk = tid + i * 256;
            int row = chunk >> 3, c = chunk & 7;
            uint32_t off = SWOFF(row, c);
            CP16(qhB + off, g_qh + qg + (size_t)row * Dsz + c * 8);
            CP16(qlB + off, g_ql + qg + (size_t)row * Dsz + c * 8);
        }
    }

    auto issue_kv = [&](int jt) {
        if (jt < nt) {
            const int js = jt * 64;
            const uint32_t base = sb + 32768 + (jt % 3) * KVSTAGE;
            const size_t kg = ((size_t)bh * Tsz + js) * Dsz;
            const size_t vg = (size_t)bh * Dsz * Tsz + js;
#pragma unroll
            for (int i = 0; i < 2; i++) {
                int chunk = tid + i * 256;
                int row = chunk >> 3, c = chunk & 7;
                uint32_t off = SWOFF(row, c);
                CP16(base + off,         g_kh + kg + (size_t)row * Dsz + c * 8);
                CP16(base + 8192 + off,  g_kl + kg + (size_t)row * Dsz + c * 8);
                CP16(base + 16384 + off, g_vt + vg + (size_t)row * Tsz + c * 8);
            }
        }
        CP_COMMIT();
    };

    issue_kv(0);
    issue_kv(1);

    float mrow[2] = { -INFINITY, -INFINITY };
    float lsum[2] = { 0.f, 0.f };
    float oa[8][4];
#pragma unroll
    for (int j = 0; j < 8; j++)
#pragma unroll
        for (int q = 0; q < 4; q++) oa[j][q] = 0.f;

    for (int jt = 0; jt < nt; jt++) {
        CP_WAITG(1);
        __syncthreads();
        issue_kv(jt + 2);

        const int js = jt * 64;
        if (js > wrow_max) continue;

        const uint32_t kvb = sb + 32768 + (jt % 3) * KVSTAGE;
        const uint32_t khB = kvb, klB = kvb + 8192;
        const uint32_t vhB = kvb + 16384;

        float s[8][4];
#pragma unroll
        for (int j = 0; j < 8; j++)
#pragma unroll
            for (int q = 0; q < 4; q++) s[j][q] = 0.f;

#pragma unroll
        for (int ks = 0; ks < 4; ks++) {
            const uint32_t cc = ks * 2 + (lane >> 4);
            uint32_t qhf[4], qlf[4];
            {
                int row = wid * 16 + lrow;
                LDM_X4(qhf[0], qhf[1], qhf[2], qhf[3], qhB + SWOFF(row, cc));
                LDM_X4(qlf[0], qlf[1], qlf[2], qlf[3], qlB + SWOFF(row, cc));
            }
#pragma unroll
            for (int jp = 0; jp < 2; jp++) {
                uint32_t khf[2][4], klf[2][4];
#pragma unroll
                for (int u = 0; u < 2; u++) {
                    int row = (jp * 2 + u) * 16 + lrow;
                    uint32_t off = SWOFF(row, cc);
                    LDM_X4(khf[u][0], khf[u][1], khf[u][2], khf[u][3], khB + off);
                    LDM_X4(klf[u][0], klf[u][1], klf[u][2], klf[u][3], klB + off);
                }
#pragma unroll
                for (int u = 0; u < 2; u++)
#pragma unroll
                    for (int o = 0; o < 2; o++) {
                        int j = 2 * (jp * 2 + u) + o;
                        MMA_BF(s[j][0], s[j][1], s[j][2], s[j][3],
                               qhf[0], qhf[1], qhf[2], qhf[3], khf[u][o], khf[u][o + 2]);
                    }
#pragma unroll
                for (int u = 0; u < 2; u++)
#pragma unroll
                    for (int o = 0; o < 2; o++) {
                        int j = 2 * (jp * 2 + u) + o;
                        MMA_BF(s[j][0], s[j][1], s[j][2], s[j][3],
                               qlf[0], qlf[1], qlf[2], qlf[3], khf[u][o], khf[u][o + 2]);
                    }
#pragma unroll
                for (int u = 0; u < 2; u++)
#pragma unroll
                    for (int o = 0; o < 2; o++) {
                        int j = 2 * (jp * 2 + u) + o;
                        MMA_BF(s[j][0], s[j][1], s[j][2], s[j][3],
                               qhf[0], qhf[1], qhf[2], qhf[3], klf[u][o], klf[u][o + 2]);
                    }
            }
        }

        if (js >= q0) {
#pragma unroll
            for (int j = 0; j < 8; j++)
#pragma unroll
                for (int q = 0; q < 4; q++) {
                    int col = js + j * 8 + 2 * (lane & 3) + (q & 1);
                    int row = q0 + wid * 16 + (lane >> 2) + (q >> 1) * 8;
                    if (col > row) s[j][q] = -INFINITY;
                }
        }

#pragma unroll
        for (int h = 0; h < 2; h++) {
            float mx = -INFINITY;
#pragma unroll
            for (int j = 0; j < 8; j++)
                mx = fmaxf(mx, fmaxf(s[j][2 * h], s[j][2 * h + 1]));
            mx = fmaxf(mx, __shfl_xor_sync(0xffffffffu, mx, 1));
            mx = fmaxf(mx, __shfl_xor_sync(0xffffffffu, mx, 2));
            float nm = fmaxf(mrow[h], mx);
            float alpha = ex2f(mrow[h] - nm);
            float sum = 0.f;
#pragma unroll
            for (int j = 0; j < 8; j++) {
                float p0 = ex2f(s[j][2 * h] - nm);
                float p1 = ex2f(s[j][2 * h + 1] - nm);
                s[j][2 * h] = p0; s[j][2 * h + 1] = p1;
                sum += p0 + p1;
            }
            lsum[h] = lsum[h] * alpha + sum;
            mrow[h] = nm;
#pragma unroll
            for (int j = 0; j < 8; j++) {
                oa[j][2 * h] *= alpha;
                oa[j][2 * h + 1] *= alpha;
            }
        }

#pragma unroll
        for (int kt2 = 0; kt2 < 4; kt2++) {
            uint32_t pa[4];
            {
                __half2 t0 = __floats2half2_rn(s[2 * kt2][0],     s[2 * kt2][1]);
                __half2 t1 = __floats2half2_rn(s[2 * kt2][2],     s[2 * kt2][3]);
                __half2 t2 = __floats2half2_rn(s[2 * kt2 + 1][0], s[2 * kt2 + 1][1]);
                __half2 t3 = __floats2half2_rn(s[2 * kt2 + 1][2], s[2 * kt2 + 1][3]);
                pa[0] = *(uint32_t*)&t0; pa[1] = *(uint32_t*)&t1;
                pa[2] = *(uint32_t*)&t2; pa[3] = *(uint32_t*)&t3;
            }
            const uint32_t cc = kt2 * 2 + (lane >> 4);
#pragma unroll
            for (int j2 = 0; j2 < 4; j2++) {
                int row = j2 * 16 + lrow;
                uint32_t off = SWOFF(row, cc);
                uint32_t vhf[4];
                LDM_X4(vhf[0], vhf[1], vhf[2], vhf[3], vhB + off);
#pragma unroll
                for (int o = 0; o < 2; o++) {
                    int j = 2 * j2 + o;
                    MMA_FP(oa[j][0], oa[j][1], oa[j][2], oa[j][3],
                           pa[0], pa[1], pa[2], pa[3], vhf[o], vhf[o + 2]);
                }
            }
        }
    }

    // Epilogue: quad-reduce lsum, y = O / l -> yh fp16
    {
        const int b = bh >> 4, hh = bh & 15;
#pragma unroll
        for (int h = 0; h < 2; h++) {
            float lt = lsum[h];
            lt += __shfl_xor_sync(0xffffffffu, lt, 1);
            lt += __shfl_xor_sync(0xffffffffu, lt, 2);
            int t = q0 + wid * 16 + (lane >> 2) + h * 8;
            float invl = 1.f / lt;
            size_t rb = ((size_t)b * Tsz + t) * KD + hh * Dsz;
#pragma unroll
            for (int j = 0; j < 8; j++) {
                int d = j * 8 + 2 * (lane & 3);
                float y0 = oa[j][2 * h] * invl;
                float y1 = oa[j][2 * h + 1] * invl;
                *(__half2*)&g_yh[rb + d] = __floats2half2_rn(y0, y1);
            }
        }
    }
}

// ---------------------------------------------------------------------------
extern "C" void kernel_launch(void* const* d_in, const int* in_sizes, int n_in,
                              void* d_out, int out_size)
{
    const float* x    = (const float*)d_in[0];
    const float* Wqkv = (const float*)d_in[1];
    const float* bqkv = (const float*)d_in[2];
    const float* Wout = (const float*)d_in[3];
    const float* bout = (const float*)d_in[4];
    float* out = (float*)d_out;

    RopeTab tab;
    for (int i = 0; i < 32; i++)
        tab.inv[i] = (float)exp(-(double)(2 * i) / 64.0 * log(10000.0));

    // 0) merged conversions
    convert_kernel<<<NB_SPLITX + NB_WQKV + NB_WOUT, 256>>>(x, Wqkv, Wout);

    // 1) Merged QKV projection
    {
        cudaFuncSetAttribute(qkv_gemm_kernel, cudaFuncAttributeMaxDynamicSharedMemorySize, QKV_SMEM);
        dim3 grid(24, M1 / 128);              // (24, 64)
        qkv_gemm_kernel<<<grid, 256, QKV_SMEM>>>(bqkv, tab);
    }

    // 2) HMMA causal flash attention -> yh
    {
        cudaFuncSetAttribute(attn_hmma_kernel, cudaFuncAttributeMaxDynamicSharedMemorySize, ATT_SMEM);
        dim3 grid(Tsz / 128, Bsz * Hsz);      // (16, 64)
        attn_hmma_kernel<<<grid, 256, ATT_SMEM>>>();
    }

    // 3) Output projection (occ-3) -> d_out
    {
        cudaFuncSetAttribute(outproj_kernel, cudaFuncAttributeMaxDynamicSharedMemorySize, OUTP_SMEM);
        dim3 grid(Csz / 128, M1 / 128);       // (8, 64)
        outproj_kernel<<<grid, 256, OUTP_SMEM>>>(bout, out);
    }
}

// round 14
// speedup vs baseline: 1.0449x; 1.0449x over previous
#include <cuda_runtime.h>
#include <cuda_bf16.h>
#include <cuda_fp16.h>
#include <math.h>
#include <stdint.h>

// Problem constants
#define Bsz 4
#define Tsz 2048
#define Csz 1024
#define Hsz 16
#define Dsz 64
#define M1 (Bsz * Tsz)        // 8192
#define KD 1024               // real K for all GEMMs

// ---------------------------------------------------------------------------
// Device scratch (allocation-free)
// ---------------------------------------------------------------------------
__device__ __nv_bfloat16 g_qh[Bsz * Hsz * Tsz * Dsz];  // (B,H,T,D)  (scaled by log2e)
__device__ __nv_bfloat16 g_ql[Bsz * Hsz * Tsz * Dsz];
__device__ __nv_bfloat16 g_kh[Bsz * Hsz * Tsz * Dsz];
__device__ __nv_bfloat16 g_kl[Bsz * Hsz * Tsz * Dsz];
__device__ __half        g_vt[Bsz * Hsz * Dsz * Tsz];  // (B,H,D,T) fp16

__device__ __nv_bfloat16 g_xh[M1 * KD];      // x bf16 hi/lo (QK GEMM)
__device__ __nv_bfloat16 g_xl[M1 * KD];
__device__ __half        g_xhf[M1 * KD];     // x fp16 hi (V GEMM, single-term)
__device__ __half        g_yh[M1 * KD];      // attn out fp16 (single-term outproj)
__device__ __nv_bfloat16 g_wqkh[2 * Csz * KD]; // W_q|k^T bf16 hi/lo
__device__ __nv_bfloat16 g_wqkl[2 * Csz * KD];
__device__ __half        g_wvh[Csz * KD];      // W_v^T fp16
__device__ __half        g_woh[Csz * KD];      // W_out^T fp16

// ---------------------------------------------------------------------------
__device__ __forceinline__ uint32_t smem_u32(const void* p) {
    uint32_t a;
    asm("{ .reg .u64 t; cvta.to.shared.u64 t, %1; cvt.u32.u64 %0, t; }" : "=r"(a) : "l"(p));
    return a;
}
__device__ __forceinline__ float ex2f(float x) {
    float r; asm("ex2.approx.ftz.f32 %0, %1;" : "=f"(r) : "f"(x)); return r;
}
__device__ __forceinline__ void split2(float v, __nv_bfloat16& hi, __nv_bfloat16& lo) {
    hi = __float2bfloat16(v);
    lo = __float2bfloat16(v - __bfloat162float(hi));
}

struct RopeTab { float inv[32]; };
#define LOG2E 1.44269504088896f

// ---------------------------------------------------------------------------
// Merged conversion kernel (one launch)
// ---------------------------------------------------------------------------
#define NB_SPLITX 8192
#define NB_WQKV   3072   // 96 x 32
#define NB_WOUT   1024   // 32 x 32

__global__ __launch_bounds__(256)
void convert_kernel(const float* __restrict__ x, const float* __restrict__ Wqkv,
                    const float* __restrict__ Wout)
{
    int blk = blockIdx.x;
    if (blk < NB_SPLITX) {
        int i = (blk * 256 + threadIdx.x) * 4;
        float4 v = *(const float4*)&x[i];
        float vv[4] = { v.x, v.y, v.z, v.w };
        __nv_bfloat16 bh[4], bl[4];
        __half fh[4];
#pragma unroll
        for (int q = 0; q < 4; q++) {
            split2(vv[q], bh[q], bl[q]);
            fh[q] = __float2half(vv[q]);
        }
        *(__nv_bfloat162*)&g_xh[i]     = __nv_bfloat162(bh[0], bh[1]);
        *(__nv_bfloat162*)&g_xh[i + 2] = __nv_bfloat162(bh[2], bh[3]);
        *(__nv_bfloat162*)&g_xl[i]     = __nv_bfloat162(bl[0], bl[1]);
        *(__nv_bfloat162*)&g_xl[i + 2] = __nv_bfloat162(bl[2], bl[3]);
        *(__half2*)&g_xhf[i]     = __half2(fh[0], fh[1]);
        *(__half2*)&g_xhf[i + 2] = __half2(fh[2], fh[3]);
        return;
    }

    __shared__ float ts[32][33];
    int ty = threadIdx.x >> 5, tx = threadIdx.x & 31;

    if (blk < NB_SPLITX + NB_WQKV) {
        int b2 = blk - NB_SPLITX;
        int n0 = (b2 % 96) * 32, k0 = (b2 / 96) * 32;
#pragma unroll
        for (int r = 0; r < 4; r++) {
            int row = ty + r * 8;
            ts[row][tx] = Wqkv[(size_t)(k0 + row) * (3 * Csz) + n0 + tx];
        }
        __syncthreads();
#pragma unroll
        for (int r = 0; r < 4; r++) {
            int row = ty + r * 8;
            int n = n0 + row;
            float v = ts[tx][row];
            if (n < 2048) {
                __nv_bfloat16 h, l; split2(v, h, l);
                g_wqkh[(size_t)n * KD + k0 + tx] = h;
                g_wqkl[(size_t)n * KD + k0 + tx] = l;
            } else {
                g_wvh[(size_t)(n - 2048) * KD + k0 + tx] = __float2half(v);
            }
        }
    } else {
        int b2 = blk - NB_SPLITX - NB_WQKV;
        int n0 = (b2 % 32) * 32, k0 = (b2 / 32) * 32;
#pragma unroll
        for (int r = 0; r < 4; r++) {
            int row = ty + r * 8;
            ts[row][tx] = Wout[(size_t)(k0 + row) * Csz + n0 + tx];
        }
        __syncthreads();
#pragma unroll
        for (int r = 0; r < 4; r++) {
            int row = ty + r * 8;
            g_woh[(size_t)(n0 + row) * KD + k0 + tx] = __float2half(ts[tx][row]);
        }
    }
}

// ---------------------------------------------------------------------------
// HMMA / async macros
// ---------------------------------------------------------------------------
#define LDM_X4(r0, r1, r2, r3, addr) \
    asm volatile("ldmatrix.sync.aligned.m8n8.x4.shared.b16 {%0,%1,%2,%3}, [%4];" \
                 : "=r"(r0), "=r"(r1), "=r"(r2), "=r"(r3) : "r"(addr))

#define MMA_BF(c0, c1, c2, c3, a0, a1, a2, a3, b0, b1) \
    asm volatile("mma.sync.aligned.m16n8k16.row.col.f32.bf16.bf16.f32 " \
                 "{%0,%1,%2,%3}, {%4,%5,%6,%7}, {%8,%9}, {%0,%1,%2,%3};" \
                 : "+f"(c0), "+f"(c1), "+f"(c2), "+f"(c3) \
                 : "r"(a0), "r"(a1), "r"(a2), "r"(a3), "r"(b0), "r"(b1))

#define MMA_FP(c0, c1, c2, c3, a0, a1, a2, a3, b0, b1) \
    asm volatile("mma.sync.aligned.m16n8k16.row.col.f32.f16.f16.f32 " \
                 "{%0,%1,%2,%3}, {%4,%5,%6,%7}, {%8,%9}, {%0,%1,%2,%3};" \
                 : "+f"(c0), "+f"(c1), "+f"(c2), "+f"(c3) \
                 : "r"(a0), "r"(a1), "r"(a2), "r"(a3), "r"(b0), "r"(b1))

#define CP16(sa, gp) \
    asm volatile("cp.async.cg.shared.global [%0], [%1], 16;" :: "r"(sa), "l"(gp))
#define CP_COMMIT() asm volatile("cp.async.commit_group;" ::: "memory")
#define CP_WAITG(n) asm volatile("cp.async.wait_group %0;" :: "n"(n) : "memory")

#define SWOFF(row, c) ((row) * 128 + (((c) ^ ((row) & 7)) * 16))
#define SWOFF32(row, c) ((row) * 64 + ((((c) ^ ((row) & 3)) ^ (((row) >> 2) & 1)) * 16))

#define TILE32 8192
#define TRS 272
#define QKV_SMEM (3 * 4 * TILE32)   // 98304

// ---------------------------------------------------------------------------
// Merged QKV GEMM. grid (24, 64).
//   blockIdx.x < 16 : QK (bf16x3) + fused RoPE (+log2e on q) split epilogue
//   blockIdx.x >= 16: V  (fp16 single-term) + transpose epilogue -> (B,H,D,T)
// ---------------------------------------------------------------------------
__global__ __launch_bounds__(256, 2)
void qkv_gemm_kernel(const float* __restrict__ bqkv, RopeTab tab)
{
    extern __shared__ char smem_all[];

    const int tid = threadIdx.x;
    const int lane = tid & 31;
    const int wid = tid >> 5;
    const int wm = wid >> 1;
    const int wn = wid & 1;
    const int m0 = blockIdx.y * 128;
    const uint32_t sbase = smem_u32(smem_all);
    const uint32_t lrow = lane & 15;
    const int nk = KD / 32;             // 32

    float acc[2][8][4];
#pragma unroll
    for (int i = 0; i < 2; i++)
#pragma unroll
        for (int j = 0; j < 8; j++)
#pragma unroll
            for (int q = 0; q < 4; q++) acc[i][j][q] = 0.f;

    if (blockIdx.x < 16) {
        // ================= QK path: bf16 3-term =================
        const int n0 = blockIdx.x * 128;
        constexpr int STAGE = 4 * TILE32;

        auto issue_stage = [&](int kt) {
            if (kt < nk) {
                const uint32_t base = sbase + (kt % 3) * STAGE;
                const __nv_bfloat16* pAh = g_xh + (size_t)m0 * KD + kt * 32;
                const __nv_bfloat16* pAl = g_xl + (size_t)m0 * KD + kt * 32;
                const __nv_bfloat16* pBh = g_wqkh + (size_t)n0 * KD + kt * 32;
                const __nv_bfloat16* pBl = g_wqkl + (size_t)n0 * KD + kt * 32;
#pragma unroll
                for (int i = 0; i < 2; i++) {
                    int chunk = tid + i * 256;
                    int row = chunk >> 2, c = chunk & 3;
                    uint32_t off = SWOFF32(row, c);
                    const size_t g = (size_t)row * KD + c * 8;
                    CP16(base + off,              pAh + g);
                    CP16(base + TILE32 + off,     pAl + g);
                    CP16(base + 2 * TILE32 + off, pBh + g);
                    CP16(base + 3 * TILE32 + off, pBl + g);
                }
            }
            CP_COMMIT();
        };

        issue_stage(0);
        issue_stage(1);

        for (int kt = 0; kt < nk; kt++) {
            CP_WAITG(1);
            __syncthreads();
            const uint32_t aBase  = sbase + (kt % 3) * STAGE;
            const uint32_t alBase = aBase + TILE32;
            const uint32_t bBase  = aBase + 2 * TILE32;
            const uint32_t blBase = aBase + 3 * TILE32;
#pragma unroll
            for (int ks = 0; ks < 2; ks++) {
                const uint32_t cc = ks * 2 + (lane >> 4);
                uint32_t ahf[2][4], alf[2][4];
#pragma unroll
                for (int i = 0; i < 2; i++) {
                    int row = wm * 32 + i * 16 + lrow;
                    LDM_X4(ahf[i][0], ahf[i][1], ahf[i][2], ahf[i][3], aBase  + SWOFF32(row, cc));
                    LDM_X4(alf[i][0], alf[i][1], alf[i][2], alf[i][3], alBase + SWOFF32(row, cc));
                }
                if (ks == 0) issue_stage(kt + 2);
#pragma unroll
                for (int j2 = 0; j2 < 4; j2++) {
                    int row = wn * 64 + j2 * 16 + lrow;
                    uint32_t bh4[4], bl4[4];
                    LDM_X4(bh4[0], bh4[1], bh4[2], bh4[3], bBase  + SWOFF32(row, cc));
                    LDM_X4(bl4[0], bl4[1], bl4[2], bl4[3], blBase + SWOFF32(row, cc));
#pragma unroll
                    for (int o = 0; o < 2; o++)
#pragma unroll
                        for (int i = 0; i < 2; i++) {
                            int j = 2 * j2 + o;
                            MMA_BF(acc[i][j][0], acc[i][j][1], acc[i][j][2], acc[i][j][3],
                                   ahf[i][0], ahf[i][1], ahf[i][2], ahf[i][3], bh4[o], bh4[o + 2]);
                        }
#pragma unroll
                    for (int o = 0; o < 2; o++)
#pragma unroll
                        for (int i = 0; i < 2; i++) {
                            int j = 2 * j2 + o;
                            MMA_BF(acc[i][j][0], acc[i][j][1], acc[i][j][2], acc[i][j][3],
                                   alf[i][0], alf[i][1], alf[i][2], alf[i][3], bh4[o], bh4[o + 2]);
                        }
#pragma unroll
                    for (int o = 0; o < 2; o++)
#pragma unroll
                        for (int i = 0; i < 2; i++) {
                            int j = 2 * j2 + o;
                            MMA_BF(acc[i][j][0], acc[i][j][1], acc[i][j][2], acc[i][j][3],
                                   ahf[i][0], ahf[i][1], ahf[i][2], ahf[i][3], bl4[o], bl4[o + 2]);
                        }
                }
            }
        }

        // Epilogue: RoPE + split; q additionally scaled by log2e
        const int which = n0 >> 10;          // 0=q, 1=k
        const float l2e = (which == 0) ? LOG2E : 1.f;
        __nv_bfloat16* GH = (which == 0) ? g_qh : g_kh;
        __nv_bfloat16* GL = (which == 0) ? g_ql : g_kl;
        const int b = m0 >> 11;
        const int hh = ((n0 + wn * 64) & 1023) >> 6;
        const int bh = b * Hsz + hh;
        const int dbase = 2 * (lane & 3);
#pragma unroll
        for (int i = 0; i < 2; i++) {
#pragma unroll
            for (int hf = 0; hf < 2; hf++) {
                int m = m0 + wm * 32 + (lane >> 2) + i * 16 + hf * 8;
                int t = m & (Tsz - 1);
                size_t baseo = ((size_t)bh * Tsz + t) * Dsz;
#pragma unroll
                for (int j = 0; j < 4; j++) {
                    int n = n0 + wn * 64 + dbase + j * 8;
                    int d = n & 63;
                    float lowx  = acc[i][j][hf * 2]     + bqkv[n];
                    float lowy  = acc[i][j][hf * 2 + 1] + bqkv[n + 1];
                    float highx = acc[i][j + 4][hf * 2]     + bqkv[n + 32];
                    float highy = acc[i][j + 4][hf * 2 + 1] + bqkv[n + 33];
                    float c0f, s0f, c1f, s1f;
                    sincosf((float)t * tab.inv[d],     &s0f, &c0f);
                    sincosf((float)t * tab.inv[d + 1], &s1f, &c1f);
                    float nlx = (lowx * c0f - highx * s0f) * l2e;
                    float nhx = (highx * c0f + lowx * s0f) * l2e;
                    float nly = (lowy * c1f - highy * s1f) * l2e;
                    float nhy = (highy * c1f + lowy * s1f) * l2e;
                    __nv_bfloat16 hlx, llx, hly, lly, hhx, lhx, hhy, lhy;
                    split2(nlx, hlx, llx); split2(nly, hly, lly);
                    split2(nhx, hhx, lhx); split2(nhy, hhy, lhy);
                    *(__nv_bfloat162*)&GH[baseo + d]      = __nv_bfloat162(hlx, hly);
                    *(__nv_bfloat162*)&GL[baseo + d]      = __nv_bfloat162(llx, lly);
                    *(__nv_bfloat162*)&GH[baseo + d + 32] = __nv_bfloat162(hhx, hhy);
                    *(__nv_bfloat162*)&GL[baseo + d + 32] = __nv_bfloat162(lhx, lhy);
                }
            }
        }
    } else {
        // ================= V path: fp16 single-term =================
        const int n0 = (blockIdx.x - 16) * 128;
        constexpr int STAGE = 2 * TILE32;

        auto issue_stage = [&](int kt) {
            if (kt < nk) {
                const uint32_t base = sbase + (kt % 3) * STAGE;
                const __half* pAh = g_xhf + (size_t)m0 * KD + kt * 32;
                const __half* pBh = g_wvh + (size_t)n0 * KD + kt * 32;
#pragma unroll
                for (int i = 0; i < 2; i++) {
                    int chunk = tid + i * 256;
                    int row = chunk >> 2, c = chunk & 3;
                    uint32_t off = SWOFF32(row, c);
                    const size_t g = (size_t)row * KD + c * 8;
                    CP16(base + off,          pAh + g);
                    CP16(base + TILE32 + off, pBh + g);
                }
            }
            CP_COMMIT();
        };

        issue_stage(0);
        issue_stage(1);

        for (int kt = 0; kt < nk; kt++) {
            CP_WAITG(1);
            __syncthreads();
            const uint32_t aBase = sbase + (kt % 3) * STAGE;
            const uint32_t bBase = aBase + TILE32;
#pragma unroll
            for (int ks = 0; ks < 2; ks++) {
                const uint32_t cc = ks * 2 + (lane >> 4);
                uint32_t ahf[2][4];
#pragma unroll
                for (int i = 0; i < 2; i++) {
                    int row = wm * 32 + i * 16 + lrow;
                    LDM_X4(ahf[i][0], ahf[i][1], ahf[i][2], ahf[i][3], aBase + SWOFF32(row, cc));
                }
                if (ks == 0) issue_stage(kt + 2);
#pragma unroll
                for (int j2 = 0; j2 < 4; j2++) {
                    int row = wn * 64 + j2 * 16 + lrow;
                    uint32_t bh4[4];
                    LDM_X4(bh4[0], bh4[1], bh4[2], bh4[3], bBase + SWOFF32(row, cc));
#pragma unroll
                    for (int o = 0; o < 2; o++)
#pragma unroll
                        for (int i = 0; i < 2; i++) {
                            int j = 2 * j2 + o;
                            MMA_FP(acc[i][j][0], acc[i][j][1], acc[i][j][2], acc[i][j][3],
                                   ahf[i][0], ahf[i][1], ahf[i][2], ahf[i][3], bh4[o], bh4[o + 2]);
                        }
                }
            }
        }

        // V epilogue: smem transpose -> g_vt (B,H,D,T) fp16
        const int b = m0 >> 11;
        const int t0 = m0 & (Tsz - 1);
        __half* trs = (__half*)smem_all;
        __syncthreads();
#pragma unroll
        for (int i = 0; i < 2; i++)
#pragma unroll
            for (int hf = 0; hf < 2; hf++) {
                int ml = wm * 32 + (lane >> 2) + i * 16 + hf * 8;
#pragma unroll
                for (int j = 0; j < 8; j++) {
                    int nl = wn * 64 + 2 * (lane & 3) + j * 8;
                    float vx = acc[i][j][hf * 2]     + bqkv[2048 + n0 + nl];
                    float vy = acc[i][j][hf * 2 + 1] + bqkv[2048 + n0 + nl + 1];
                    trs[nl * 136 + ml]       = __float2half(vx);
                    trs[(nl + 1) * 136 + ml] = __float2half(vy);
                }
            }
        __syncthreads();
#pragma unroll
        for (int rr = 0; rr < 8; rr++) {
            int row = (tid >> 4) + rr * 16;
            int chunk = tid & 15;
            int n = n0 + row;
            int hh = n >> 6;
            int d = n & 63;
            float4 v = *(float4*)((char*)trs + row * TRS + chunk * 16);
            *(float4*)&g_vt[((size_t)(b * Hsz + hh) * Dsz + d) * Tsz + t0 + chunk * 8] = v;
        }
    }
}

// ---------------------------------------------------------------------------
// Output projection: fp16 single-term (yh @ Woh). occ-2, 4-stage pipeline.
// ---------------------------------------------------------------------------
#define OUTP_SMEM (4 * 2 * TILE32)   // 65536

__global__ __launch_bounds__(256, 2)
void outproj_kernel(const float* __restrict__ bias, float* __restrict__ Cout)
{
    extern __shared__ char smem_all[];
    const int tid = threadIdx.x;
    const int lane = tid & 31;
    const int wid = tid >> 5;
    const int wm = wid >> 1;
    const int wn = wid & 1;
    const int m0 = blockIdx.y * 128;
    const int n0 = blockIdx.x * 128;
    const uint32_t sbase = smem_u32(smem_all);
    const uint32_t lrow = lane & 15;
    const int nk = KD / 32;
    constexpr int STAGE = 2 * TILE32;

    auto issue_stage = [&](int kt) {
        if (kt < nk) {
            const uint32_t base = sbase + (kt & 3) * STAGE;
            const __half* pAh = g_yh + (size_t)m0 * KD + kt * 32;
            const __half* pBh = g_woh + (size_t)n0 * KD + kt * 32;
#pragma unroll
            for (int i = 0; i < 2; i++) {
                int chunk = tid + i * 256;
                int row = chunk >> 2, c = chunk & 3;
                uint32_t off = SWOFF32(row, c);
                const size_t g = (size_t)row * KD + c * 8;
                CP16(base + off,          pAh + g);
                CP16(base + TILE32 + off, pBh + g);
            }
        }
        CP_COMMIT();
    };

    issue_stage(0);
    issue_stage(1);
    issue_stage(2);

    float acc[2][8][4];
#pragma unroll
    for (int i = 0; i < 2; i++)
#pragma unroll
        for (int j = 0; j < 8; j++)
#pragma unroll
            for (int q = 0; q < 4; q++) acc[i][j][q] = 0.f;

    for (int kt = 0; kt < nk; kt++) {
        CP_WAITG(2);
        __syncthreads();
        issue_stage(kt + 3);   // overwrites buffer (kt-1)&3: safe past the barrier
        const uint32_t aBase = sbase + (kt & 3) * STAGE;
        const uint32_t bBase = aBase + TILE32;
#pragma unroll
        for (int ks = 0; ks < 2; ks++) {
            const uint32_t cc = ks * 2 + (lane >> 4);
            uint32_t ahf[2][4];
#pragma unroll
            for (int i = 0; i < 2; i++) {
                int row = wm * 32 + i * 16 + lrow;
                LDM_X4(ahf[i][0], ahf[i][1], ahf[i][2], ahf[i][3], aBase + SWOFF32(row, cc));
            }
#pragma unroll
            for (int j2 = 0; j2 < 4; j2++) {
                int row = wn * 64 + j2 * 16 + lrow;
                uint32_t bh4[4];
                LDM_X4(bh4[0], bh4[1], bh4[2], bh4[3], bBase + SWOFF32(row, cc));
#pragma unroll
                for (int o = 0; o < 2; o++)
#pragma unroll
                    for (int i = 0; i < 2; i++) {
                        int j = 2 * j2 + o;
                        MMA_FP(acc[i][j][0], acc[i][j][1], acc[i][j][2], acc[i][j][3],
                               ahf[i][0], ahf[i][1], ahf[i][2], ahf[i][3], bh4[o], bh4[o + 2]);
                    }
            }
        }
    }

    const int mwb = m0 + wm * 32 + (lane >> 2);
    const int nwb = n0 + wn * 64 + 2 * (lane & 3);
#pragma unroll
    for (int i = 0; i < 2; i++)
#pragma unroll
        for (int j = 0; j < 8; j++) {
            int n = nwb + j * 8;
            float bx = bias[n], by = bias[n + 1];
#pragma unroll
            for (int hf = 0; hf < 2; hf++) {
                int m = mwb + i * 16 + hf * 8;
                *(float2*)&Cout[(size_t)m * Csz + n] =
                    make_float2(acc[i][j][hf * 2] + bx, acc[i][j][hf * 2 + 1] + by);
            }
        }
}

// ---------------------------------------------------------------------------
// HMMA flash attention, causal. BM=128 (8 warps x 16 rows), BN=64, D=64.
// S: bf16x3 (ex2 softmax). PV: fp16 single-term. 3-stage KV; per-warp skip.
// ---------------------------------------------------------------------------
#define KVSTAGE 24576
#define ATT_SMEM (32768 + 3 * KVSTAGE)      // 106496

__global__ __launch_bounds__(256, 2)
void attn_hmma_kernel()
{
    extern __shared__ char asmem[];

    const int tid = threadIdx.x;
    const int lane = tid & 31;
    const int wid = tid >> 5;              // 0..7
    const int q0 = (int)(gridDim.x - 1 - blockIdx.x) * 128;
    const int bh = blockIdx.y;
    const uint32_t sb = smem_u32(asmem);
    const uint32_t qhB = sb, qlB = sb + 16384;
    const uint32_t lrow = lane & 15;
    const int nt = q0 / 64 + 2;
    const int wrow_max = q0 + wid * 16 + 15;

    {
        const size_t qg = ((size_t)bh * Tsz + q0) * Dsz;
#pragma unroll
        for (int i = 0; i < 4; i++) {
            int chunk = tid + i * 256;
            int row = chunk >> 3, c = chunk & 7;
            uint32_t off = SWOFF(row, c);
            CP16(qhB + off, g_qh + qg + (size_t)row * Dsz + c * 8);
            CP16(qlB + off, g_ql + qg + (size_t)row * Dsz + c * 8);
        }
    }

    auto issue_kv = [&](int jt) {
        if (jt < nt) {
            const int js = jt * 64;
            const uint32_t base = sb + 32768 + (jt % 3) * KVSTAGE;
            const size_t kg = ((size_t)bh * Tsz + js) * Dsz;
            const size_t vg = (size_t)bh * Dsz * Tsz + js;
#pragma unroll
            for (int i = 0; i < 2; i++) {
                int chunk = tid + i * 256;
                int row = chunk >> 3, c = chunk & 7;
                uint32_t off = SWOFF(row, c);
                CP16(base + off,         g_kh + kg + (size_t)row * Dsz + c * 8);
                CP16(base + 8192 + off,  g_kl + kg + (size_t)row * Dsz + c * 8);
                CP16(base + 16384 + off, g_vt + vg + (size_t)row * Tsz + c * 8);
            }
        }
        CP_COMMIT();
    };

    issue_kv(0);
    issue_kv(1);

    float mrow[2] = { -INFINITY, -INFINITY };
    float lsum[2] = { 0.f, 0.f };
    float oa[8][4];
#pragma unroll
    for (int j = 0; j < 8; j++)
#pragma unroll
        for (int q = 0; q < 4; q++) oa[j][q] = 0.f;

    for (int jt = 0; jt < nt; jt++) {
        CP_WAITG(1);
        __syncthreads();
        issue_kv(jt + 2);

        const int js = jt * 64;
        if (js > wrow_max) continue;

        const uint32_t kvb = sb + 32768 + (jt % 3) * KVSTAGE;
        const uint32_t khB = kvb, klB = kvb + 8192;
        const uint32_t vhB = kvb + 16384;

        float s[8][4];
#pragma unroll
        for (int j = 0; j < 8; j++)
#pragma unroll
            for (int q = 0; q < 4; q++) s[j][q] = 0.f;

#pragma unroll
        for (int ks = 0; ks < 4; ks++) {
            const uint32_t cc = ks * 2 + (lane >> 4);
            uint32_t qhf[4], qlf[4];
            {
                int row = wid * 16 + lrow;
                LDM_X4(qhf[0], qhf[1], qhf[2], qhf[3], qhB + SWOFF(row, cc));
                LDM_X4(qlf[0], qlf[1], qlf[2], qlf[3], qlB + SWOFF(row, cc));
            }
#pragma unroll
            for (int jp = 0; jp < 2; jp++) {
                uint32_t khf[2][4], klf[2][4];
#pragma unroll
                for (int u = 0; u < 2; u++) {
                    int row = (jp * 2 + u) * 16 + lrow;
                    uint32_t off = SWOFF(row, cc);
                    LDM_X4(khf[u][0], khf[u][1], khf[u][2], khf[u][3], khB + off);
                    LDM_X4(klf[u][0], klf[u][1], klf[u][2], klf[u][3], klB + off);
                }
#pragma unroll
                for (int u = 0; u < 2; u++)
#pragma unroll
                    for (int o = 0; o < 2; o++) {
                        int j = 2 * (jp * 2 + u) + o;
                        MMA_BF(s[j][0], s[j][1], s[j][2], s[j][3],
                               qhf[0], qhf[1], qhf[2], qhf[3], khf[u][o], khf[u][o + 2]);
                    }
#pragma unroll
                for (int u = 0; u < 2; u++)
#pragma unroll
                    for (int o = 0; o < 2; o++) {
                        int j = 2 * (jp * 2 + u) + o;
                        MMA_BF(s[j][0], s[j][1], s[j][2], s[j][3],
                               qlf[0], qlf[1], qlf[2], qlf[3], khf[u][o], khf[u][o + 2]);
                    }
#pragma unroll
                for (int u = 0; u < 2; u++)
#pragma unroll
                    for (int o = 0; o < 2; o++) {
                        int j = 2 * (jp * 2 + u) + o;
                        MMA_BF(s[j][0], s[j][1], s[j][2], s[j][3],
                               qhf[0], qhf[1], qhf[2], qhf[3], klf[u][o], klf[u][o + 2]);
                    }
            }
        }

        if (js >= q0) {
#pragma unroll
            for (int j = 0; j < 8; j++)
#pragma unroll
                for (int q = 0; q < 4; q++) {
                    int col = js + j * 8 + 2 * (lane & 3) + (q & 1);
                    int row = q0 + wid * 16 + (lane >> 2) + (q >> 1) * 8;
                    if (col > row) s[j][q] = -INFINITY;
                }
        }

#pragma unroll
        for (int h = 0; h < 2; h++) {
            float mx = -INFINITY;
#pragma unroll
            for (int j = 0; j < 8; j++)
                mx = fmaxf(mx, fmaxf(s[j][2 * h], s[j][2 * h + 1]));
            mx = fmaxf(mx, __shfl_xor_sync(0xffffffffu, mx, 1));
            mx = fmaxf(mx, __shfl_xor_sync(0xffffffffu, mx, 2));
            float nm = fmaxf(mrow[h], mx);
            float alpha = ex2f(mrow[h] - nm);
            float sum = 0.f;
#pragma unroll
            for (int j = 0; j < 8; j++) {
                float p0 = ex2f(s[j][2 * h] - nm);
                float p1 = ex2f(s[j][2 * h + 1] - nm);
                s[j][2 * h] = p0; s[j][2 * h + 1] = p1;
                sum += p0 + p1;
            }
            lsum[h] = lsum[h] * alpha + sum;
            mrow[h] = nm;
#pragma unroll
            for (int j = 0; j < 8; j++) {
                oa[j][2 * h] *= alpha;
                oa[j][2 * h + 1] *= alpha;
            }
        }

#pragma unroll
        for (int kt2 = 0; kt2 < 4; kt2++) {
            uint32_t pa[4];
            {
                __half2 t0 = __floats2half2_rn(s[2 * kt2][0],     s[2 * kt2][1]);
                __half2 t1 = __floats2half2_rn(s[2 * kt2][2],     s[2 * kt2][3]);
                __half2 t2 = __floats2half2_rn(s[2 * kt2 + 1][0], s[2 * kt2 + 1][1]);
                __half2 t3 = __floats2half2_rn(s[2 * kt2 + 1][2], s[2 * kt2 + 1][3]);
                pa[0] = *(uint32_t*)&t0; pa[1] = *(uint32_t*)&t1;
                pa[2] = *(uint32_t*)&t2; pa[3] = *(uint32_t*)&t3;
            }
            const uint32_t cc = kt2 * 2 + (lane >> 4);
#pragma unroll
            for (int j2 = 0; j2 < 4; j2++) {
                int row = j2 * 16 + lrow;
                uint32_t off = SWOFF(row, cc);
                uint32_t vhf[4];
                LDM_X4(vhf[0], vhf[1], vhf[2], vhf[3], vhB + off);
#pragma unroll
                for (int o = 0; o < 2; o++) {
                    int j = 2 * j2 + o;
                    MMA_FP(oa[j][0], oa[j][1], oa[j][2], oa[j][3],
                           pa[0], pa[1], pa[2], pa[3], vhf[o], vhf[o + 2]);
                }
            }
        }
    }

    // Epilogue: quad-reduce lsum, y = O / l -> yh fp16
    {
        const int b = bh >> 4, hh = bh & 15;
#pragma unroll
        for (int h = 0; h < 2; h++) {
            float lt = lsum[h];
            lt += __shfl_xor_sync(0xffffffffu, lt, 1);
            lt += __shfl_xor_sync(0xffffffffu, lt, 2);
            int t = q0 + wid * 16 + (lane >> 2) + h * 8;
            float invl = 1.f / lt;
            size_t rb = ((size_t)b * Tsz + t) * KD + hh * Dsz;
#pragma unroll
            for (int j = 0; j < 8; j++) {
                int d = j * 8 + 2 * (lane & 3);
                float y0 = oa[j][2 * h] * invl;
                float y1 = oa[j][2 * h + 1] * invl;
                *(__half2*)&g_yh[rb + d] = __floats2half2_rn(y0, y1);
            }
        }
    }
}

// ---------------------------------------------------------------------------
extern "C" void kernel_launch(void* const* d_in, const int* in_sizes, int n_in,
                              void* d_out, int out_size)
{
    const float* x    = (const float*)d_in[0];
    const float* Wqkv = (const float*)d_in[1];
    const float* bqkv = (const float*)d_in[2];
    const float* Wout = (const float*)d_in[3];
    const float* bout = (const float*)d_in[4];
    float* out = (float*)d_out;

    RopeTab tab;
    for (int i = 0; i < 32; i++)
        tab.inv[i] = (float)exp(-(double)(2 * i) / 64.0 * log(10000.0));

    // 0) merged conversions
    convert_kernel<<<NB_SPLITX + NB_WQKV + NB_WOUT, 256>>>(x, Wqkv, Wout);

    // 1) Merged QKV projection
    {
        cudaFuncSetAttribute(qkv_gemm_kernel, cudaFuncAttributeMaxDynamicSharedMemorySize, QKV_SMEM);
        dim3 grid(24, M1 / 128);              // (24, 64)
        qkv_gemm_kernel<<<grid, 256, QKV_SMEM>>>(bqkv, tab);
    }

    // 2) HMMA causal flash attention -> yh
    {
        cudaFuncSetAttribute(attn_hmma_kernel, cudaFuncAttributeMaxDynamicSharedMemorySize, ATT_SMEM);
        dim3 grid(Tsz / 128, Bsz * Hsz);      // (16, 64)
        attn_hmma_kernel<<<grid, 256, ATT_SMEM>>>();
    }

    // 3) Output projection (occ-2, 4-stage) -> d_out
    {
        cudaFuncSetAttribute(outproj_kernel, cudaFuncAttributeMaxDynamicSharedMemorySize, OUTP_SMEM);
        dim3 grid(Csz / 128, M1 / 128);       // (8, 64)
        outproj_kernel<<<grid, 256, OUTP_SMEM>>>(bout, out);
    }
}

// round 15
// speedup vs baseline: 1.0457x; 1.0008x over previous
#include <cuda_runtime.h>
#include <cuda_bf16.h>
#include <cuda_fp16.h>
#include <math.h>
#include <stdint.h>

// Problem constants
#define Bsz 4
#define Tsz 2048
#define Csz 1024
#define Hsz 16
#define Dsz 64
#define M1 (Bsz * Tsz)        // 8192
#define KD 1024               // real K for all GEMMs

// ---------------------------------------------------------------------------
// Device scratch (allocation-free)
// ---------------------------------------------------------------------------
__device__ __nv_bfloat16 g_qh[Bsz * Hsz * Tsz * Dsz];  // (B,H,T,D)  (scaled by log2e)
__device__ __nv_bfloat16 g_ql[Bsz * Hsz * Tsz * Dsz];
__device__ __nv_bfloat16 g_kh[Bsz * Hsz * Tsz * Dsz];
__device__ __nv_bfloat16 g_kl[Bsz * Hsz * Tsz * Dsz];
__device__ __half        g_vt[Bsz * Hsz * Dsz * Tsz];  // (B,H,D,T) fp16

__device__ __nv_bfloat16 g_xh[M1 * KD];      // x bf16 hi/lo (QK GEMM)
__device__ __nv_bfloat16 g_xl[M1 * KD];
__device__ __half        g_xhf[M1 * KD];     // x fp16 hi (V GEMM, single-term)
__device__ __half        g_yh[M1 * KD];      // attn out fp16 (single-term outproj)
__device__ __nv_bfloat16 g_wqkh[2 * Csz * KD]; // W_q|k^T bf16 hi/lo
__device__ __nv_bfloat16 g_wqkl[2 * Csz * KD];
__device__ __half        g_wvh[Csz * KD];      // W_v^T fp16
__device__ __half        g_woh[Csz * KD];      // W_out^T fp16

// ---------------------------------------------------------------------------
__device__ __forceinline__ uint32_t smem_u32(const void* p) {
    uint32_t a;
    asm("{ .reg .u64 t; cvta.to.shared.u64 t, %1; cvt.u32.u64 %0, t; }" : "=r"(a) : "l"(p));
    return a;
}
__device__ __forceinline__ float ex2f(float x) {
    float r; asm("ex2.approx.ftz.f32 %0, %1;" : "=f"(r) : "f"(x)); return r;
}
__device__ __forceinline__ void split2(float v, __nv_bfloat16& hi, __nv_bfloat16& lo) {
    hi = __float2bfloat16(v);
    lo = __float2bfloat16(v - __bfloat162float(hi));
}

struct RopeTab { float inv[32]; };
#define LOG2E 1.44269504088896f

// ---------------------------------------------------------------------------
// Merged conversion kernel (one launch)
// ---------------------------------------------------------------------------
#define NB_SPLITX 8192
#define NB_WQKV   3072   // 96 x 32
#define NB_WOUT   1024   // 32 x 32

__global__ __launch_bounds__(256)
void convert_kernel(const float* __restrict__ x, const float* __restrict__ Wqkv,
                    const float* __restrict__ Wout)
{
    int blk = blockIdx.x;
    if (blk < NB_SPLITX) {
        int i = (blk * 256 + threadIdx.x) * 4;
        float4 v = *(const float4*)&x[i];
        float vv[4] = { v.x, v.y, v.z, v.w };
        __nv_bfloat16 bh[4], bl[4];
        __half fh[4];
#pragma unroll
        for (int q = 0; q < 4; q++) {
            split2(vv[q], bh[q], bl[q]);
            fh[q] = __float2half(vv[q]);
        }
        *(__nv_bfloat162*)&g_xh[i]     = __nv_bfloat162(bh[0], bh[1]);
        *(__nv_bfloat162*)&g_xh[i + 2] = __nv_bfloat162(bh[2], bh[3]);
        *(__nv_bfloat162*)&g_xl[i]     = __nv_bfloat162(bl[0], bl[1]);
        *(__nv_bfloat162*)&g_xl[i + 2] = __nv_bfloat162(bl[2], bl[3]);
        *(__half2*)&g_xhf[i]     = __half2(fh[0], fh[1]);
        *(__half2*)&g_xhf[i + 2] = __half2(fh[2], fh[3]);
        return;
    }

    __shared__ float ts[32][33];
    int ty = threadIdx.x >> 5, tx = threadIdx.x & 31;

    if (blk < NB_SPLITX + NB_WQKV) {
        int b2 = blk - NB_SPLITX;
        int n0 = (b2 % 96) * 32, k0 = (b2 / 96) * 32;
#pragma unroll
        for (int r = 0; r < 4; r++) {
            int row = ty + r * 8;
            ts[row][tx] = Wqkv[(size_t)(k0 + row) * (3 * Csz) + n0 + tx];
        }
        __syncthreads();
#pragma unroll
        for (int r = 0; r < 4; r++) {
            int row = ty + r * 8;
            int n = n0 + row;
            float v = ts[tx][row];
            if (n < 2048) {
                __nv_bfloat16 h, l; split2(v, h, l);
                g_wqkh[(size_t)n * KD + k0 + tx] = h;
                g_wqkl[(size_t)n * KD + k0 + tx] = l;
            } else {
                g_wvh[(size_t)(n - 2048) * KD + k0 + tx] = __float2half(v);
            }
        }
    } else {
        int b2 = blk - NB_SPLITX - NB_WQKV;
        int n0 = (b2 % 32) * 32, k0 = (b2 / 32) * 32;
#pragma unroll
        for (int r = 0; r < 4; r++) {
            int row = ty + r * 8;
            ts[row][tx] = Wout[(size_t)(k0 + row) * Csz + n0 + tx];
        }
        __syncthreads();
#pragma unroll
        for (int r = 0; r < 4; r++) {
            int row = ty + r * 8;
            g_woh[(size_t)(n0 + row) * KD + k0 + tx] = __float2half(ts[tx][row]);
        }
    }
}

// ---------------------------------------------------------------------------
// HMMA / async macros
// ---------------------------------------------------------------------------
#define LDM_X4(r0, r1, r2, r3, addr) \
    asm volatile("ldmatrix.sync.aligned.m8n8.x4.shared.b16 {%0,%1,%2,%3}, [%4];" \
                 : "=r"(r0), "=r"(r1), "=r"(r2), "=r"(r3) : "r"(addr))

#define MMA_BF(c0, c1, c2, c3, a0, a1, a2, a3, b0, b1) \
    asm volatile("mma.sync.aligned.m16n8k16.row.col.f32.bf16.bf16.f32 " \
                 "{%0,%1,%2,%3}, {%4,%5,%6,%7}, {%8,%9}, {%0,%1,%2,%3};" \
                 : "+f"(c0), "+f"(c1), "+f"(c2), "+f"(c3) \
                 : "r"(a0), "r"(a1), "r"(a2), "r"(a3), "r"(b0), "r"(b1))

#define MMA_FP(c0, c1, c2, c3, a0, a1, a2, a3, b0, b1) \
    asm volatile("mma.sync.aligned.m16n8k16.row.col.f32.f16.f16.f32 " \
                 "{%0,%1,%2,%3}, {%4,%5,%6,%7}, {%8,%9}, {%0,%1,%2,%3};" \
                 : "+f"(c0), "+f"(c1), "+f"(c2), "+f"(c3) \
                 : "r"(a0), "r"(a1), "r"(a2), "r"(a3), "r"(b0), "r"(b1))

#define CP16(sa, gp) \
    asm volatile("cp.async.cg.shared.global [%0], [%1], 16;" :: "r"(sa), "l"(gp))
#define CP_COMMIT() asm volatile("cp.async.commit_group;" ::: "memory")
#define CP_WAITG(n) asm volatile("cp.async.wait_group %0;" :: "n"(n) : "memory")

#define SWOFF(row, c) ((row) * 128 + (((c) ^ ((row) & 7)) * 16))
#define SWOFF32(row, c) ((row) * 64 + ((((c) ^ ((row) & 3)) ^ (((row) >> 2) & 1)) * 16))

#define TILE32 8192
#define TRS 272
#define QKV_SMEM (3 * 4 * TILE32)   // 98304

// ---------------------------------------------------------------------------
// Merged QKV GEMM. grid (24, 64).
//   blockIdx.x < 16 : QK (bf16x3) + fused RoPE (+log2e on q) split epilogue
//   blockIdx.x >= 16: V  (fp16 single-term) + transpose epilogue -> (B,H,D,T)
// ---------------------------------------------------------------------------
__global__ __launch_bounds__(256, 2)
void qkv_gemm_kernel(const float* __restrict__ bqkv, RopeTab tab)
{
    extern __shared__ char smem_all[];

    const int tid = threadIdx.x;
    const int lane = tid & 31;
    const int wid = tid >> 5;
    const int wm = wid >> 1;
    const int wn = wid & 1;
    const int m0 = blockIdx.y * 128;
    const uint32_t sbase = smem_u32(smem_all);
    const uint32_t lrow = lane & 15;
    const int nk = KD / 32;             // 32

    float acc[2][8][4];
#pragma unroll
    for (int i = 0; i < 2; i++)
#pragma unroll
        for (int j = 0; j < 8; j++)
#pragma unroll
            for (int q = 0; q < 4; q++) acc[i][j][q] = 0.f;

    if (blockIdx.x < 16) {
        // ================= QK path: bf16 3-term =================
        const int n0 = blockIdx.x * 128;
        constexpr int STAGE = 4 * TILE32;

        auto issue_stage = [&](int kt) {
            if (kt < nk) {
                const uint32_t base = sbase + (kt % 3) * STAGE;
                const __nv_bfloat16* pAh = g_xh + (size_t)m0 * KD + kt * 32;
                const __nv_bfloat16* pAl = g_xl + (size_t)m0 * KD + kt * 32;
                const __nv_bfloat16* pBh = g_wqkh + (size_t)n0 * KD + kt * 32;
                const __nv_bfloat16* pBl = g_wqkl + (size_t)n0 * KD + kt * 32;
#pragma unroll
                for (int i = 0; i < 2; i++) {
                    int chunk = tid + i * 256;
                    int row = chunk >> 2, c = chunk & 3;
                    uint32_t off = SWOFF32(row, c);
                    const size_t g = (size_t)row * KD + c * 8;
                    CP16(base + off,              pAh + g);
                    CP16(base + TILE32 + off,     pAl + g);
                    CP16(base + 2 * TILE32 + off, pBh + g);
                    CP16(base + 3 * TILE32 + off, pBl + g);
                }
            }
            CP_COMMIT();
        };

        issue_stage(0);
        issue_stage(1);

        for (int kt = 0; kt < nk; kt++) {
            CP_WAITG(1);
            __syncthreads();
            const uint32_t aBase  = sbase + (kt % 3) * STAGE;
            const uint32_t alBase = aBase + TILE32;
            const uint32_t bBase  = aBase + 2 * TILE32;
            const uint32_t blBase = aBase + 3 * TILE32;
#pragma unroll
            for (int ks = 0; ks < 2; ks++) {
                const uint32_t cc = ks * 2 + (lane >> 4);
                uint32_t ahf[2][4], alf[2][4];
#pragma unroll
                for (int i = 0; i < 2; i++) {
                    int row = wm * 32 + i * 16 + lrow;
                    LDM_X4(ahf[i][0], ahf[i][1], ahf[i][2], ahf[i][3], aBase  + SWOFF32(row, cc));
                    LDM_X4(alf[i][0], alf[i][1], alf[i][2], alf[i][3], alBase + SWOFF32(row, cc));
                }
                if (ks == 0) issue_stage(kt + 2);
#pragma unroll
                for (int j2 = 0; j2 < 4; j2++) {
                    int row = wn * 64 + j2 * 16 + lrow;
                    uint32_t bh4[4], bl4[4];
                    LDM_X4(bh4[0], bh4[1], bh4[2], bh4[3], bBase  + SWOFF32(row, cc));
                    LDM_X4(bl4[0], bl4[1], bl4[2], bl4[3], blBase + SWOFF32(row, cc));
#pragma unroll
                    for (int o = 0; o < 2; o++)
#pragma unroll
                        for (int i = 0; i < 2; i++) {
                            int j = 2 * j2 + o;
                            MMA_BF(acc[i][j][0], acc[i][j][1], acc[i][j][2], acc[i][j][3],
                                   ahf[i][0], ahf[i][1], ahf[i][2], ahf[i][3], bh4[o], bh4[o + 2]);
                        }
#pragma unroll
                    for (int o = 0; o < 2; o++)
#pragma unroll
                        for (int i = 0; i < 2; i++) {
                            int j = 2 * j2 + o;
                            MMA_BF(acc[i][j][0], acc[i][j][1], acc[i][j][2], acc[i][j][3],
                                   alf[i][0], alf[i][1], alf[i][2], alf[i][3], bh4[o], bh4[o + 2]);
                        }
#pragma unroll
                    for (int o = 0; o < 2; o++)
#pragma unroll
                        for (int i = 0; i < 2; i++) {
                            int j = 2 * j2 + o;
                            MMA_BF(acc[i][j][0], acc[i][j][1], acc[i][j][2], acc[i][j][3],
                                   ahf[i][0], ahf[i][1], ahf[i][2], ahf[i][3], bl4[o], bl4[o + 2]);
                        }
                }
            }
        }

        // Epilogue: RoPE + split; q additionally scaled by log2e
        const int which = n0 >> 10;          // 0=q, 1=k
        const float l2e = (which == 0) ? LOG2E : 1.f;
        __nv_bfloat16* GH = (which == 0) ? g_qh : g_kh;
        __nv_bfloat16* GL = (which == 0) ? g_ql : g_kl;
        const int b = m0 >> 11;
        const int hh = ((n0 + wn * 64) & 1023) >> 6;
        const int bh = b * Hsz + hh;
        const int dbase = 2 * (lane & 3);
#pragma unroll
        for (int i = 0; i < 2; i++) {
#pragma unroll
            for (int hf = 0; hf < 2; hf++) {
                int m = m0 + wm * 32 + (lane >> 2) + i * 16 + hf * 8;
                int t = m & (Tsz - 1);
                size_t baseo = ((size_t)bh * Tsz + t) * Dsz;
#pragma unroll
                for (int j = 0; j < 4; j++) {
                    int n = n0 + wn * 64 + dbase + j * 8;
                    int d = n & 63;
                    float lowx  = acc[i][j][hf * 2]     + bqkv[n];
                    float lowy  = acc[i][j][hf * 2 + 1] + bqkv[n + 1];
                    float highx = acc[i][j + 4][hf * 2]     + bqkv[n + 32];
                    float highy = acc[i][j + 4][hf * 2 + 1] + bqkv[n + 33];
                    float c0f, s0f, c1f, s1f;
                    sincosf((float)t * tab.inv[d],     &s0f, &c0f);
                    sincosf((float)t * tab.inv[d + 1], &s1f, &c1f);
                    float nlx = (lowx * c0f - highx * s0f) * l2e;
                    float nhx = (highx * c0f + lowx * s0f) * l2e;
                    float nly = (lowy * c1f - highy * s1f) * l2e;
                    float nhy = (highy * c1f + lowy * s1f) * l2e;
                    __nv_bfloat16 hlx, llx, hly, lly, hhx, lhx, hhy, lhy;
                    split2(nlx, hlx, llx); split2(nly, hly, lly);
                    split2(nhx, hhx, lhx); split2(nhy, hhy, lhy);
                    *(__nv_bfloat162*)&GH[baseo + d]      = __nv_bfloat162(hlx, hly);
                    *(__nv_bfloat162*)&GL[baseo + d]      = __nv_bfloat162(llx, lly);
                    *(__nv_bfloat162*)&GH[baseo + d + 32] = __nv_bfloat162(hhx, hhy);
                    *(__nv_bfloat162*)&GL[baseo + d + 32] = __nv_bfloat162(lhx, lhy);
                }
            }
        }
    } else {
        // ================= V path: fp16 single-term =================
        const int n0 = (blockIdx.x - 16) * 128;
        constexpr int STAGE = 2 * TILE32;

        auto issue_stage = [&](int kt) {
            if (kt < nk) {
                const uint32_t base = sbase + (kt % 3) * STAGE;
                const __half* pAh = g_xhf + (size_t)m0 * KD + kt * 32;
                const __half* pBh = g_wvh + (size_t)n0 * KD + kt * 32;
#pragma unroll
                for (int i = 0; i < 2; i++) {
                    int chunk = tid + i * 256;
                    int row = chunk >> 2, c = chunk & 3;
                    uint32_t off = SWOFF32(row, c);
                    const size_t g = (size_t)row * KD + c * 8;
                    CP16(base + off,          pAh + g);
                    CP16(base + TILE32 + off, pBh + g);
                }
            }
            CP_COMMIT();
        };

        issue_stage(0);
        issue_stage(1);

        for (int kt = 0; kt < nk; kt++) {
            CP_WAITG(1);
            __syncthreads();
            const uint32_t aBase = sbase + (kt % 3) * STAGE;
            const uint32_t bBase = aBase + TILE32;
#pragma unroll
            for (int ks = 0; ks < 2; ks++) {
                const uint32_t cc = ks * 2 + (lane >> 4);
                uint32_t ahf[2][4];
#pragma unroll
                for (int i = 0; i < 2; i++) {
                    int row = wm * 32 + i * 16 + lrow;
                    LDM_X4(ahf[i][0], ahf[i][1], ahf[i][2], ahf[i][3], aBase + SWOFF32(row, cc));
                }
                if (ks == 0) issue_stage(kt + 2);
#pragma unroll
                for (int j2 = 0; j2 < 4; j2++) {
                    int row = wn * 64 + j2 * 16 + lrow;
                    uint32_t bh4[4];
                    LDM_X4(bh4[0], bh4[1], bh4[2], bh4[3], bBase + SWOFF32(row, cc));
#pragma unroll
                    for (int o = 0; o < 2; o++)
#pragma unroll
                        for (int i = 0; i < 2; i++) {
                            int j = 2 * j2 + o;
                            MMA_FP(acc[i][j][0], acc[i][j][1], acc[i][j][2], acc[i][j][3],
                                   ahf[i][0], ahf[i][1], ahf[i][2], ahf[i][3], bh4[o], bh4[o + 2]);
                        }
                }
            }
        }

        // V epilogue: smem transpose -> g_vt (B,H,D,T) fp16
        const int b = m0 >> 11;
        const int t0 = m0 & (Tsz - 1);
        __half* trs = (__half*)smem_all;
        __syncthreads();
#pragma unroll
        for (int i = 0; i < 2; i++)
#pragma unroll
            for (int hf = 0; hf < 2; hf++) {
                int ml = wm * 32 + (lane >> 2) + i * 16 + hf * 8;
#pragma unroll
                for (int j = 0; j < 8; j++) {
                    int nl = wn * 64 + 2 * (lane & 3) + j * 8;
                    float vx = acc[i][j][hf * 2]     + bqkv[2048 + n0 + nl];
                    float vy = acc[i][j][hf * 2 + 1] + bqkv[2048 + n0 + nl + 1];
                    trs[nl * 136 + ml]       = __float2half(vx);
                    trs[(nl + 1) * 136 + ml] = __float2half(vy);
                }
            }
        __syncthreads();
#pragma unroll
        for (int rr = 0; rr < 8; rr++) {
            int row = (tid >> 4) + rr * 16;
            int chunk = tid & 15;
            int n = n0 + row;
            int hh = n >> 6;
            int d = n & 63;
            float4 v = *(float4*)((char*)trs + row * TRS + chunk * 16);
            *(float4*)&g_vt[((size_t)(b * Hsz + hh) * Dsz + d) * Tsz + t0 + chunk * 8] = v;
        }
    }
}

// ---------------------------------------------------------------------------
// Output projection: fp16 single-term (yh @ Woh).
// BM=128 x BN=64, 8 warps x 16-row strips, occ-3, 4-stage pipeline.
// ---------------------------------------------------------------------------
#define OP_ATILE 8192      // 128 rows x 64B
#define OP_BTILE 4096      // 64 rows x 64B
#define OP_STAGE (OP_ATILE + OP_BTILE)   // 12288
#define OUTP_SMEM (4 * OP_STAGE)         // 49152

__global__ __launch_bounds__(256, 3)
void outproj_kernel(const float* __restrict__ bias, float* __restrict__ Cout)
{
    extern __shared__ char smem_all[];
    const int tid = threadIdx.x;
    const int lane = tid & 31;
    const int wid = tid >> 5;            // 0..7 : 16-row strip
    const int m0 = blockIdx.y * 128;
    const int n0 = blockIdx.x * 64;
    const uint32_t sbase = smem_u32(smem_all);
    const uint32_t lrow = lane & 15;
    const int nk = KD / 32;

    auto issue_stage = [&](int kt) {
        if (kt < nk) {
            const uint32_t abuf = sbase + (kt & 3) * OP_STAGE;
            const uint32_t bbuf = abuf + OP_ATILE;
            const __half* pAh = g_yh + (size_t)m0 * KD + kt * 32;
            const __half* pBh = g_woh + (size_t)n0 * KD + kt * 32;
            // A: 512 chunks -> 2/thread
#pragma unroll
            for (int i = 0; i < 2; i++) {
                int chunk = tid + i * 256;
                int row = chunk >> 2, c = chunk & 3;
                CP16(abuf + SWOFF32(row, c), pAh + (size_t)row * KD + c * 8);
            }
            // B: 256 chunks -> threads 0..255, 1 each
            {
                int row = tid >> 2, c = tid & 3;
                CP16(bbuf + SWOFF32(row, c), pBh + (size_t)row * KD + c * 8);
            }
        }
        CP_COMMIT();
    };

    issue_stage(0);
    issue_stage(1);
    issue_stage(2);

    float acc[8][4];
#pragma unroll
    for (int j = 0; j < 8; j++)
#pragma unroll
        for (int q = 0; q < 4; q++) acc[j][q] = 0.f;

    for (int kt = 0; kt < nk; kt++) {
        CP_WAITG(2);
        __syncthreads();
        issue_stage(kt + 3);
        const uint32_t aBase = sbase + (kt & 3) * OP_STAGE;
        const uint32_t bBase = aBase + OP_ATILE;
#pragma unroll
        for (int ks = 0; ks < 2; ks++) {
            const uint32_t cc = ks * 2 + (lane >> 4);
            uint32_t ahf[4];
            {
                int row = wid * 16 + lrow;
                LDM_X4(ahf[0], ahf[1], ahf[2], ahf[3], aBase + SWOFF32(row, cc));
            }
#pragma unroll
            for (int j2 = 0; j2 < 4; j2++) {
                int row = j2 * 16 + lrow;
                uint32_t bh4[4];
                LDM_X4(bh4[0], bh4[1], bh4[2], bh4[3], bBase + SWOFF32(row, cc));
#pragma unroll
                for (int o = 0; o < 2; o++) {
                    int j = 2 * j2 + o;
                    MMA_FP(acc[j][0], acc[j][1], acc[j][2], acc[j][3],
                           ahf[0], ahf[1], ahf[2], ahf[3], bh4[o], bh4[o + 2]);
                }
            }
        }
    }

    const int mwb = m0 + wid * 16 + (lane >> 2);
    const int nwb = n0 + 2 * (lane & 3);
#pragma unroll
    for (int j = 0; j < 8; j++) {
        int n = nwb + j * 8;
        float bx = bias[n], by = bias[n + 1];
#pragma unroll
        for (int hf = 0; hf < 2; hf++) {
            int m = mwb + hf * 8;
            *(float2*)&Cout[(size_t)m * Csz + n] =
                make_float2(acc[j][hf * 2] + bx, acc[j][hf * 2 + 1] + by);
        }
    }
}

// ---------------------------------------------------------------------------
// HMMA flash attention, causal. BM=128 (8 warps x 16 rows), BN=64, D=64.
// S: bf16x3 (ex2 softmax). PV: fp16 single-term. 3-stage KV; per-warp skip.
// ---------------------------------------------------------------------------
#define KVSTAGE 24576
#define ATT_SMEM (32768 + 3 * KVSTAGE)      // 106496

__global__ __launch_bounds__(256, 2)
void attn_hmma_kernel()
{
    extern __shared__ char asmem[];

    const int tid = threadIdx.x;
    const int lane = tid & 31;
    const int wid = tid >> 5;              // 0..7
    const int q0 = (int)(gridDim.x - 1 - blockIdx.x) * 128;
    const int bh = blockIdx.y;
    const uint32_t sb = smem_u32(asmem);
    const uint32_t qhB = sb, qlB = sb + 16384;
    const uint32_t lrow = lane & 15;
    const int nt = q0 / 64 + 2;
    const int wrow_max = q0 + wid * 16 + 15;

    {
        const size_t qg = ((size_t)bh * Tsz + q0) * Dsz;
#pragma unroll
        for (int i = 0; i < 4; i++) {
            int chunk = tid + i * 256;
            int row = chunk >> 3, c = chunk & 7;
            uint32_t off = SWOFF(row, c);
            CP16(qhB + off, g_qh + qg + (size_t)row * Dsz + c * 8);
            CP16(qlB + off, g_ql + qg + (size_t)row * Dsz + c * 8);
        }
    }

    auto issue_kv = [&](int jt) {
        if (jt < nt) {
            const int js = jt * 64;
            const uint32_t base = sb + 32768 + (jt % 3) * KVSTAGE;
            const size_t kg = ((size_t)bh * Tsz + js) * Dsz;
            const size_t vg = (size_t)bh * Dsz * Tsz + js;
#pragma unroll
            for (int i = 0; i < 2; i++) {
                int chunk = tid + i * 256;
                int row = chunk >> 3, c = chunk & 7;
                uint32_t off = SWOFF(row, c);
                CP16(base + off,         g_kh + kg + (size_t)row * Dsz + c * 8);
                CP16(base + 8192 + off,  g_kl + kg + (size_t)row * Dsz + c * 8);
                CP16(base + 16384 + off, g_vt + vg + (size_t)row * Tsz + c * 8);
            }
        }
        CP_COMMIT();
    };

    issue_kv(0);
    issue_kv(1);

    float mrow[2] = { -INFINITY, -INFINITY };
    float lsum[2] = { 0.f, 0.f };
    float oa[8][4];
#pragma unroll
    for (int j = 0; j < 8; j++)
#pragma unroll
        for (int q = 0; q < 4; q++) oa[j][q] = 0.f;

    for (int jt = 0; jt < nt; jt++) {
        CP_WAITG(1);
        __syncthreads();
        issue_kv(jt + 2);

        const int js = jt * 64;
        if (js > wrow_max) continue;

        const uint32_t kvb = sb + 32768 + (jt % 3) * KVSTAGE;
        const uint32_t khB = kvb, klB = kvb + 8192;
        const uint32_t vhB = kvb + 16384;

        float s[8][4];
#pragma unroll
        for (int j = 0; j < 8; j++)
#pragma unroll
            for (int q = 0; q < 4; q++) s[j][q] = 0.f;

#pragma unroll
        for (int ks = 0; ks < 4; ks++) {
            const uint32_t cc = ks * 2 + (lane >> 4);
            uint32_t qhf[4], qlf[4];
            {
                int row = wid * 16 + lrow;
                LDM_X4(qhf[0], qhf[1], qhf[2], qhf[3], qhB + SWOFF(row, cc));
                LDM_X4(qlf[0], qlf[1], qlf[2], qlf[3], qlB + SWOFF(row, cc));
            }
#pragma unroll
            for (int jp = 0; jp < 2; jp++) {
                uint32_t khf[2][4], klf[2][4];
#pragma unroll
                for (int u = 0; u < 2; u++) {
                    int row = (jp * 2 + u) * 16 + lrow;
                    uint32_t off = SWOFF(row, cc);
                    LDM_X4(khf[u][0], khf[u][1], khf[u][2], khf[u][3], khB + off);
                    LDM_X4(klf[u][0], klf[u][1], klf[u][2], klf[u][3], klB + off);
                }
#pragma unroll
                for (int u = 0; u < 2; u++)
#pragma unroll
                    for (int o = 0; o < 2; o++) {
                        int j = 2 * (jp * 2 + u) + o;
                        MMA_BF(s[j][0], s[j][1], s[j][2], s[j][3],
                               qhf[0], qhf[1], qhf[2], qhf[3], khf[u][o], khf[u][o + 2]);
                    }
#pragma unroll
                for (int u = 0; u < 2; u++)
#pragma unroll
                    for (int o = 0; o < 2; o++) {
                        int j = 2 * (jp * 2 + u) + o;
                        MMA_BF(s[j][0], s[j][1], s[j][2], s[j][3],
                               qlf[0], qlf[1], qlf[2], qlf[3], khf[u][o], khf[u][o + 2]);
                    }
#pragma unroll
                for (int u = 0; u < 2; u++)
#pragma unroll
                    for (int o = 0; o < 2; o++) {
                        int j = 2 * (jp * 2 + u) + o;
                        MMA_BF(s[j][0], s[j][1], s[j][2], s[j][3],
                               qhf[0], qhf[1], qhf[2], qhf[3], klf[u][o], klf[u][o + 2]);
                    }
            }
        }

        if (js >= q0) {
#pragma unroll
            for (int j = 0; j < 8; j++)
#pragma unroll
                for (int q = 0; q < 4; q++) {
                    int col = js + j * 8 + 2 * (lane & 3) + (q & 1);
                    int row = q0 + wid * 16 + (lane >> 2) + (q >> 1) * 8;
                    if (col > row) s[j][q] = -INFINITY;
                }
        }

#pragma unroll
        for (int h = 0; h < 2; h++) {
            float mx = -INFINITY;
#pragma unroll
            for (int j = 0; j < 8; j++)
                mx = fmaxf(mx, fmaxf(s[j][2 * h], s[j][2 * h + 1]));
            mx = fmaxf(mx, __shfl_xor_sync(0xffffffffu, mx, 1));
            mx = fmaxf(mx, __shfl_xor_sync(0xffffffffu, mx, 2));
            float nm = fmaxf(mrow[h], mx);
            float alpha = ex2f(mrow[h] - nm);
            float sum = 0.f;
#pragma unroll
            for (int j = 0; j < 8; j++) {
                float p0 = ex2f(s[j][2 * h] - nm);
                float p1 = ex2f(s[j][2 * h + 1] - nm);
                s[j][2 * h] = p0; s[j][2 * h + 1] = p1;
                sum += p0 + p1;
            }
            lsum[h] = lsum[h] * alpha + sum;
            mrow[h] = nm;
#pragma unroll
            for (int j = 0; j < 8; j++) {
                oa[j][2 * h] *= alpha;
                oa[j][2 * h + 1] *= alpha;
            }
        }

#pragma unroll
        for (int kt2 = 0; kt2 < 4; kt2++) {
            uint32_t pa[4];
            {
                __half2 t0 = __floats2half2_rn(s[2 * kt2][0],     s[2 * kt2][1]);
                __half2 t1 = __floats2half2_rn(s[2 * kt2][2],     s[2 * kt2][3]);
                __half2 t2 = __floats2half2_rn(s[2 * kt2 + 1][0], s[2 * kt2 + 1][1]);
                __half2 t3 = __floats2half2_rn(s[2 * kt2 + 1][2], s[2 * kt2 + 1][3]);
                pa[0] = *(uint32_t*)&t0; pa[1] = *(uint32_t*)&t1;
                pa[2] = *(uint32_t*)&t2; pa[3] = *(uint32_t*)&t3;
            }
            const uint32_t cc = kt2 * 2 + (lane >> 4);
#pragma unroll
            for (int j2 = 0; j2 < 4; j2++) {
                int row = j2 * 16 + lrow;
                uint32_t off = SWOFF(row, cc);
                uint32_t vhf[4];
                LDM_X4(vhf[0], vhf[1], vhf[2], vhf[3], vhB + off);
#pragma unroll
                for (int o = 0; o < 2; o++) {
                    int j = 2 * j2 + o;
                    MMA_FP(oa[j][0], oa[j][1], oa[j][2], oa[j][3],
                           pa[0], pa[1], pa[2], pa[3], vhf[o], vhf[o + 2]);
                }
            }
        }
    }

    // Epilogue: quad-reduce lsum, y = O / l -> yh fp16
    {
        const int b = bh >> 4, hh = bh & 15;
#pragma unroll
        for (int h = 0; h < 2; h++) {
            float lt = lsum[h];
            lt += __shfl_xor_sync(0xffffffffu, lt, 1);
            lt += __shfl_xor_sync(0xffffffffu, lt, 2);
            int t = q0 + wid * 16 + (lane >> 2) + h * 8;
            float invl = 1.f / lt;
            size_t rb = ((size_t)b * Tsz + t) * KD + hh * Dsz;
#pragma unroll
            for (int j = 0; j < 8; j++) {
                int d = j * 8 + 2 * (lane & 3);
                float y0 = oa[j][2 * h] * invl;
                float y1 = oa[j][2 * h + 1] * invl;
                *(__half2*)&g_yh[rb + d] = __floats2half2_rn(y0, y1);
            }
        }
    }
}

// ---------------------------------------------------------------------------
extern "C" void kernel_launch(void* const* d_in, const int* in_sizes, int n_in,
                              void* d_out, int out_size)
{
    const float* x    = (const float*)d_in[0];
    const float* Wqkv = (const float*)d_in[1];
    const float* bqkv = (const float*)d_in[2];
    const float* Wout = (const float*)d_in[3];
    const float* bout = (const float*)d_in[4];
    float* out = (float*)d_out;

    RopeTab tab;
    for (int i = 0; i < 32; i++)
        tab.inv[i] = (float)exp(-(double)(2 * i) / 64.0 * log(10000.0));

    // 0) merged conversions
    convert_kernel<<<NB_SPLITX + NB_WQKV + NB_WOUT, 256>>>(x, Wqkv, Wout);

    // 1) Merged QKV projection
    {
        cudaFuncSetAttribute(qkv_gemm_kernel, cudaFuncAttributeMaxDynamicSharedMemorySize, QKV_SMEM);
        dim3 grid(24, M1 / 128);              // (24, 64)
        qkv_gemm_kernel<<<grid, 256, QKV_SMEM>>>(bqkv, tab);
    }

    // 2) HMMA causal flash attention -> yh
    {
        cudaFuncSetAttribute(attn_hmma_kernel, cudaFuncAttributeMaxDynamicSharedMemorySize, ATT_SMEM);
        dim3 grid(Tsz / 128, Bsz * Hsz);      // (16, 64)
        attn_hmma_kernel<<<grid, 256, ATT_SMEM>>>();
    }

    // 3) Output projection (BM128xBN64, occ-3, 4-stage) -> d_out
    {
        cudaFuncSetAttribute(outproj_kernel, cudaFuncAttributeMaxDynamicSharedMemorySize, OUTP_SMEM);
        dim3 grid(Csz / 64, M1 / 128);        // (16, 64)
        outproj_kernel<<<grid, 256, OUTP_SMEM>>>(bout, out);
    }
}